// round 6
// baseline (speedup 1.0000x reference)
#include <cuda_runtime.h>
#include <cuda_bf16.h>
#include <math.h>

// Problem constants
#define TT   128
#define BB   64
#define HH   512
#define VV   10000
#define G3   1536   // 3*H
#define G2   1024   // 2*H
#define MB   (TT*BB)   // 8192 rows

// ---------------- device scratch (static: no allocations allowed) ----------
__device__ float g_h0[BB*HH];
__device__ float g_h1[BB*HH];
__device__ float g_z0[BB*HH];
__device__ float g_rh0[BB*HH];
__device__ float g_z1[BB*HH];
__device__ float g_rh1[BB*HH];
__device__ float g_whx1[BB*HH];
__device__ float g_GX0[MB*G3];       // 50.3 MB  precomputed layer0 input gates
__device__ float g_M1[HH*G3];        // 3 MB     fc0^T @ W_x1
__device__ float g_b1p[G3];
__device__ float g_Dmt[VV*HH];       // 20.5 MB  dec_W @ fc1  (V x H)
__device__ float g_db2[VV];
__device__ float g_Hseq[MB*HH];      // 16.8 MB  h1 per step

// ---------------- generic tiled GEMM 128x128x16 ----------------------------
// C[M,N] = opA(A) @ opB(B) (+ bias[n]).  OPA: 0 = A is MxK row-major,
// 1 = A stored KxM (use transpose).  OPB: 0 = B is KxN, 1 = B stored NxK (NT).
// GATHER: row of A taken from gidx[m] (embedding gather).
template<int OPA, int OPB, bool GATHER, bool BIAS>
__global__ __launch_bounds__(256, 1)
void gemm128(const float* __restrict__ A, const float* __restrict__ B,
             const float* __restrict__ bias, const int* __restrict__ gidx,
             float* __restrict__ C, int M, int N, int K)
{
    const int BM = 128, BN = 128, BK = 16;
    __shared__ float As[BK][BM];
    __shared__ float Bs[BK][BN];
    const int m0 = blockIdx.y * BM;
    const int n0 = blockIdx.x * BN;
    const int tid = threadIdx.x;
    const int tm0 = (tid & 15) * 8;
    const int tn0 = (tid >> 4) * 8;
    float acc[8][8];
#pragma unroll
    for (int i = 0; i < 8; i++)
#pragma unroll
        for (int j = 0; j < 8; j++) acc[i][j] = 0.f;

    for (int k0 = 0; k0 < K; k0 += BK) {
        // ---- load A tile ----
        if (OPA == 0) {
            int kk = tid & 15, mr = tid >> 4;
#pragma unroll
            for (int i = 0; i < 8; i++) {
                int m = mr + i * 16;
                int gm = m0 + m;
                float v = 0.f;
                if (gm < M) {
                    long row = GATHER ? (long)gidx[gm] : (long)gm;
                    v = A[row * K + k0 + kk];
                }
                As[kk][m] = v;
            }
        } else {
            int m = tid & 127, kb = tid >> 7;
#pragma unroll
            for (int i = 0; i < 8; i++) {
                int kk = kb + i * 2;
                int gm = m0 + m;
                As[kk][m] = (gm < M) ? A[(long)(k0 + kk) * M + gm] : 0.f;
            }
        }
        // ---- load B tile ----
        if (OPB == 0) {
            int n = tid & 127, kb = tid >> 7;
#pragma unroll
            for (int i = 0; i < 8; i++) {
                int kk = kb + i * 2;
                int gn = n0 + n;
                Bs[kk][n] = (gn < N) ? B[(long)(k0 + kk) * N + gn] : 0.f;
            }
        } else {
            int kk = tid & 15, nr = tid >> 4;
#pragma unroll
            for (int i = 0; i < 8; i++) {
                int n = nr + i * 16;
                int gn = n0 + n;
                Bs[kk][n] = (gn < N) ? B[(long)gn * K + k0 + kk] : 0.f;
            }
        }
        __syncthreads();
#pragma unroll
        for (int kk = 0; kk < BK; kk++) {
            float a[8], b[8];
            *(float4*)&a[0] = *(const float4*)&As[kk][tm0];
            *(float4*)&a[4] = *(const float4*)&As[kk][tm0 + 4];
            *(float4*)&b[0] = *(const float4*)&Bs[kk][tn0];
            *(float4*)&b[4] = *(const float4*)&Bs[kk][tn0 + 4];
#pragma unroll
            for (int i = 0; i < 8; i++)
#pragma unroll
                for (int j = 0; j < 8; j++)
                    acc[i][j] += a[i] * b[j];
        }
        __syncthreads();
    }
#pragma unroll
    for (int i = 0; i < 8; i++) {
        int gm = m0 + tm0 + i;
        if (gm >= M) continue;
#pragma unroll
        for (int j = 0; j < 8; j++) {
            int gn = n0 + tn0 + j;
            if (gn < N) {
                float v = acc[i][j];
                if (BIAS) v += bias[gn];
                C[(long)gm * N + gn] = v;
            }
        }
    }
}

// ---------------- one-time small precomputes -------------------------------
__global__ void compute_b1p(const float* __restrict__ fcb0,
                            const float* __restrict__ Wx1,
                            const float* __restrict__ brzh1,
                            float* __restrict__ out)
{
    int j = blockIdx.x * 256 + threadIdx.x;
    if (j >= G3) return;
    float s = brzh1[j];
    for (int m = 0; m < HH; m++) s += fcb0[m] * Wx1[m * G3 + j];
    out[j] = s;
}

__global__ void compute_db2(const float* __restrict__ fcb1,
                            const float* __restrict__ decW,
                            const float* __restrict__ decb,
                            float* __restrict__ out)
{
    int v = (blockIdx.x * 256 + threadIdx.x) >> 5;
    int lane = threadIdx.x & 31;
    if (v >= VV) return;
    float s = 0.f;
    for (int j = lane; j < HH; j += 32) s += fcb1[j] * decW[v * HH + j];
#pragma unroll
    for (int o = 16; o; o >>= 1) s += __shfl_xor_sync(0xffffffffu, s, o);
    if (lane == 0) out[v] = s + decb[v];
}

__global__ void init_h(const float* __restrict__ hidden)
{
    int i = blockIdx.x * 256 + threadIdx.x;
    if (i < BB * HH) {
        g_h0[i] = hidden[i];
        g_h1[i] = hidden[BB * HH + i];
    }
}

__global__ void write_hfinal(float* __restrict__ out)
{
    int i = blockIdx.x * 256 + threadIdx.x;
    if (i < BB * HH) {
        out[i] = g_h0[i];
        out[BB * HH + i] = g_h1[i];
    }
}

// ---------------- recurrent step kernels -----------------------------------
// s0_gates: r,z for layer0.  512 threads = 2 gates x 16 batch x 16 h.
// grid (32 h-tiles, 4 b-tiles).
__global__ __launch_bounds__(512)
void s0_gates(const float* __restrict__ Uh0, const float* __restrict__ gx0t)
{
    __shared__ float sh[16][128];
    const int tid = threadIdx.x;
    const int b0 = blockIdx.y * 16;
    const int h  = blockIdx.x * 16 + (tid & 15);
    const int g  = tid >> 8;
    const int bb = (tid >> 4) & 15;
    const int col = g * HH + h;
    float a0 = 0.f, a1 = 0.f, a2 = 0.f, a3 = 0.f;
    for (int kc = 0; kc < HH; kc += 128) {
        for (int e = tid; e < 2048; e += 512)
            sh[e >> 7][e & 127] = g_h0[(b0 + (e >> 7)) * HH + kc + (e & 127)];
        __syncthreads();
#pragma unroll 8
        for (int k = 0; k < 128; k += 4) {
            a0 += sh[bb][k + 0] * Uh0[(kc + k + 0) * G2 + col];
            a1 += sh[bb][k + 1] * Uh0[(kc + k + 1) * G2 + col];
            a2 += sh[bb][k + 2] * Uh0[(kc + k + 2) * G2 + col];
            a3 += sh[bb][k + 3] * Uh0[(kc + k + 3) * G2 + col];
        }
        __syncthreads();
    }
    float acc = (a0 + a1) + (a2 + a3);
    int b = b0 + bb;
    float gx = gx0t[b * G3 + col];
    float v = 1.f / (1.f + expf(-(gx + acc)));
    if (g == 0) g_rh0[b * HH + h] = v * g_h0[b * HH + h];
    else        g_z0[b * HH + h]  = v;
}

// s1_gates: layer1 gates from h0_new (via merged M1) and h1 (via U_h1).
// 512 threads = 16 batch x 32 h; grid (16 h-tiles, 4 b-tiles). 5 dots/thread.
__global__ __launch_bounds__(512)
void s1_gates(const float* __restrict__ Uh1)
{
    __shared__ float s0[16][128];
    __shared__ float s1[16][128];
    const int tid = threadIdx.x;
    const int b0 = blockIdx.y * 16;
    const int h  = blockIdx.x * 32 + (tid & 31);
    const int bb = tid >> 5;
    float ar = 0.f, az = 0.f, aw = 0.f, br = 0.f, bz = 0.f;
    for (int kc = 0; kc < HH; kc += 128) {
        for (int e = tid; e < 2048; e += 512) {
            int r = e >> 7, c = e & 127;
            s0[r][c] = g_h0[(b0 + r) * HH + kc + c];
            s1[r][c] = g_h1[(b0 + r) * HH + kc + c];
        }
        __syncthreads();
#pragma unroll 4
        for (int k = 0; k < 128; k++) {
            float x0 = s0[bb][k], x1 = s1[bb][k];
            int kk = kc + k;
            ar += x0 * g_M1[kk * G3 + h];
            az += x0 * g_M1[kk * G3 + HH + h];
            aw += x0 * g_M1[kk * G3 + 2 * HH + h];
            br += x1 * Uh1[kk * G2 + h];
            bz += x1 * Uh1[kk * G2 + HH + h];
        }
        __syncthreads();
    }
    int b = b0 + bb;
    float r = 1.f / (1.f + expf(-(ar + br + g_b1p[h])));
    float z = 1.f / (1.f + expf(-(az + bz + g_b1p[HH + h])));
    g_z1[b * HH + h]   = z;
    g_rh1[b * HH + h]  = r * g_h1[b * HH + h];
    g_whx1[b * HH + h] = aw + g_b1p[2 * HH + h];
}

// s_update: h_new = (1-z)h + z tanh(whx + (r*h)@U_ht). 512 thr = 16b x 32h.
// grid (16 h-tiles, 4 b-tiles).
__global__ __launch_bounds__(512)
void s_update(const float* __restrict__ Uht, const float* __restrict__ rh,
              const float* __restrict__ zb, float* __restrict__ hst,
              const float* __restrict__ whx, int whx_stride,
              float* __restrict__ hseq)
{
    __shared__ float sh[16][128];
    const int tid = threadIdx.x;
    const int b0 = blockIdx.y * 16;
    const int h  = blockIdx.x * 32 + (tid & 31);
    const int bb = tid >> 5;
    float a0 = 0.f, a1 = 0.f, a2 = 0.f, a3 = 0.f;
    for (int kc = 0; kc < HH; kc += 128) {
        for (int e = tid; e < 2048; e += 512)
            sh[e >> 7][e & 127] = rh[(b0 + (e >> 7)) * HH + kc + (e & 127)];
        __syncthreads();
#pragma unroll 8
        for (int k = 0; k < 128; k += 4) {
            a0 += sh[bb][k + 0] * Uht[(kc + k + 0) * HH + h];
            a1 += sh[bb][k + 1] * Uht[(kc + k + 1) * HH + h];
            a2 += sh[bb][k + 2] * Uht[(kc + k + 2) * HH + h];
            a3 += sh[bb][k + 3] * Uht[(kc + k + 3) * HH + h];
        }
        __syncthreads();
    }
    int b = b0 + bb;
    float ht = tanhf(whx[b * whx_stride + h] + ((a0 + a1) + (a2 + a3)));
    float z  = zb[b * HH + h];
    float hp = hst[b * HH + h];
    float hn = hp + z * (ht - hp);
    hst[b * HH + h] = hn;
    if (hseq) hseq[b * HH + h] = hn;
}

// ---------------- host launch ----------------------------------------------
extern "C" void kernel_launch(void* const* d_in, const int* in_sizes, int n_in,
                              void* d_out, int out_size)
{
    const int*   inputs = (const int*)  d_in[0];            // (T,B)
    const float* hidden = (const float*)d_in[1];            // (2,B,H)
    const float* embt   = (const float*)d_in[2];            // (V,E)
    const float* W_x    = (const float*)d_in[3];            // (2,H,3H)
    const float* U_h    = (const float*)d_in[4];            // (2,H,2H)
    const float* U_ht   = (const float*)d_in[5];            // (2,H,H)
    const float* b_rzh  = (const float*)d_in[6];            // (2,3H)
    const float* fc_W   = (const float*)d_in[7];            // (2,H,H)
    const float* fc_b   = (const float*)d_in[8];            // (2,H)
    const float* dec_W  = (const float*)d_in[9];            // (V,H)
    const float* dec_b  = (const float*)d_in[10];           // (V,)
    float* out = (float*)d_out;

    const float* W_x0  = W_x;
    const float* W_x1  = W_x + HH * G3;
    const float* U_h0  = U_h;
    const float* U_h1  = U_h + HH * G2;
    const float* U_ht0 = U_ht;
    const float* U_ht1 = U_ht + HH * HH;
    const float* fc0   = fc_W;
    const float* fc1   = fc_W + HH * HH;

    float* pGX0  = nullptr; cudaGetSymbolAddress((void**)&pGX0,  g_GX0);
    float* pM1   = nullptr; cudaGetSymbolAddress((void**)&pM1,   g_M1);
    float* pB1p  = nullptr; cudaGetSymbolAddress((void**)&pB1p,  g_b1p);
    float* pDmt  = nullptr; cudaGetSymbolAddress((void**)&pDmt,  g_Dmt);
    float* pDb2  = nullptr; cudaGetSymbolAddress((void**)&pDb2,  g_db2);
    float* pHseq = nullptr; cudaGetSymbolAddress((void**)&pHseq, g_Hseq);
    float* pRh0  = nullptr; cudaGetSymbolAddress((void**)&pRh0,  g_rh0);
    float* pZ0   = nullptr; cudaGetSymbolAddress((void**)&pZ0,   g_z0);
    float* pRh1  = nullptr; cudaGetSymbolAddress((void**)&pRh1,  g_rh1);
    float* pZ1   = nullptr; cudaGetSymbolAddress((void**)&pZ1,   g_z1);
    float* pWhx1 = nullptr; cudaGetSymbolAddress((void**)&pWhx1, g_whx1);
    float* pH0   = nullptr; cudaGetSymbolAddress((void**)&pH0,   g_h0);
    float* pH1   = nullptr; cudaGetSymbolAddress((void**)&pH1,   g_h1);

    // 0) load initial hidden state
    init_h<<<(BB * HH + 255) / 256, 256>>>(hidden);

    // 1) GX0 = gather(emb)[8192 x 512] @ W_x0[512 x 1536] + b_rzh0
    gemm128<0, 0, true, true><<<dim3(G3 / 128, MB / 128), 256>>>(
        embt, W_x0, b_rzh, inputs, pGX0, MB, G3, HH);

    // 2) M1 = fc0^T @ W_x1, b1' = fc_b0 @ W_x1 + b_rzh1
    gemm128<1, 0, false, false><<<dim3(G3 / 128, HH / 128), 256>>>(
        fc0, W_x1, nullptr, nullptr, pM1, HH, G3, HH);
    compute_b1p<<<(G3 + 255) / 256, 256>>>(fc_b, W_x1, b_rzh + G3, pB1p);

    // 3) Dmt = dec_W @ fc1  (V x H), db2 = dec_W @ fc_b1 + dec_b
    gemm128<0, 0, false, false><<<dim3(HH / 128, (VV + 127) / 128), 256>>>(
        dec_W, fc1, nullptr, nullptr, pDmt, VV, HH, HH);
    compute_db2<<<(VV * 32 + 255) / 256, 256>>>(fc_b + HH, dec_W, dec_b, pDb2);

    // 4) recurrent loop: 4 small fused GEMM kernels per timestep
    for (int t = 0; t < TT; t++) {
        const float* gx0t = pGX0 + (long)t * BB * G3;
        s0_gates<<<dim3(32, 4), 512>>>(U_h0, gx0t);
        s_update<<<dim3(16, 4), 512>>>(U_ht0, pRh0, pZ0, pH0,
                                       gx0t + 2 * HH, G3, nullptr);
        s1_gates<<<dim3(16, 4), 512>>>(U_h1);
        s_update<<<dim3(16, 4), 512>>>(U_ht1, pRh1, pZ1, pH1,
                                       pWhx1, HH, pHseq + (long)t * BB * HH);
    }

    // 5) logits = Hseq[8192 x 512] @ Dmt^T[512 x 10000] + db2
    gemm128<0, 1, false, true><<<dim3((VV + 127) / 128, MB / 128), 256>>>(
        pHseq, pDmt, pDb2, nullptr, out, MB, VV, HH);

    // 6) h_final = [h0, h1] appended after logits (if harness expects it)
    if (out_size >= (long)MB * VV + 2 * BB * HH) {
        write_hfinal<<<(BB * HH + 255) / 256, 256>>>(out + (long)MB * VV);
    }
}

// round 7
// speedup vs baseline: 2.9222x; 2.9222x over previous
#include <cuda_runtime.h>
#include <cuda_bf16.h>
#include <math.h>

// Problem constants
#define TT   128
#define BB   64
#define HH   512
#define VV   10000
#define G3   1536   // 3*H
#define G2   1024   // 2*H
#define MB   (TT*BB)   // 8192 rows
#define NBLK 128       // persistent blocks (<=148 SMs, 1/SM guaranteed)
#define CH   4         // h-columns owned per block (NBLK*CH = HH)

// ---------------- device scratch (static: no allocations allowed) ----------
__device__ unsigned g_bar;                 // grid barrier counter
__device__ float g_h0T[HH*BB];             // transposed activations [h][b]
__device__ float g_h1T[HH*BB];
__device__ float g_rh0T[HH*BB];
__device__ float g_rh1T[HH*BB];
__device__ float g_gx0T[(long)MB*G3];      // 50.3 MB, layout [t][col][b]
__device__ float g_M1[HH*G3];              // fc0^T @ W_x1
__device__ float g_b1p[G3];
__device__ float g_Dmt[(long)VV*HH];       // dec_W @ fc1  (V x H)
__device__ float g_db2[VV];
__device__ float g_Hseq[(long)MB*HH];      // h1 per step, [t][b][h] (decoder layout)

// ---------------- generic tiled GEMM 128x128x16 ----------------------------
// C = opA(A) @ opB(B) (+bias). OPA: 0 = MxK row-major, 1 = stored KxM.
// OPB: 0 = KxN, 1 = NxK (NT). GATHER: A row via gidx[m].
// TOUT: write C transposed per 64-row group: C[((m>>6)*N + n)*64 + (m&63)].
template<int OPA, int OPB, bool GATHER, bool BIAS, bool TOUT>
__global__ __launch_bounds__(256, 1)
void gemm128(const float* __restrict__ A, const float* __restrict__ B,
             const float* __restrict__ bias, const int* __restrict__ gidx,
             float* __restrict__ C, int M, int N, int K)
{
    const int BM = 128, BN = 128, BK = 16;
    __shared__ float As[BK][BM];
    __shared__ float Bs[BK][BN];
    const int m0 = blockIdx.y * BM;
    const int n0 = blockIdx.x * BN;
    const int tid = threadIdx.x;
    const int tm0 = (tid & 15) * 8;
    const int tn0 = (tid >> 4) * 8;
    float acc[8][8];
#pragma unroll
    for (int i = 0; i < 8; i++)
#pragma unroll
        for (int j = 0; j < 8; j++) acc[i][j] = 0.f;

    for (int k0 = 0; k0 < K; k0 += BK) {
        if (OPA == 0) {
            int kk = tid & 15, mr = tid >> 4;
#pragma unroll
            for (int i = 0; i < 8; i++) {
                int m = mr + i * 16;
                int gm = m0 + m;
                float v = 0.f;
                if (gm < M) {
                    long row = GATHER ? (long)gidx[gm] : (long)gm;
                    v = A[row * K + k0 + kk];
                }
                As[kk][m] = v;
            }
        } else {
            int m = tid & 127, kb = tid >> 7;
#pragma unroll
            for (int i = 0; i < 8; i++) {
                int kk = kb + i * 2;
                int gm = m0 + m;
                As[kk][m] = (gm < M) ? A[(long)(k0 + kk) * M + gm] : 0.f;
            }
        }
        if (OPB == 0) {
            int n = tid & 127, kb = tid >> 7;
#pragma unroll
            for (int i = 0; i < 8; i++) {
                int kk = kb + i * 2;
                int gn = n0 + n;
                Bs[kk][n] = (gn < N) ? B[(long)(k0 + kk) * N + gn] : 0.f;
            }
        } else {
            int kk = tid & 15, nr = tid >> 4;
#pragma unroll
            for (int i = 0; i < 8; i++) {
                int n = nr + i * 16;
                int gn = n0 + n;
                Bs[kk][n] = (gn < N) ? B[(long)gn * K + k0 + kk] : 0.f;
            }
        }
        __syncthreads();
#pragma unroll
        for (int kk = 0; kk < BK; kk++) {
            float a[8], b[8];
            *(float4*)&a[0] = *(const float4*)&As[kk][tm0];
            *(float4*)&a[4] = *(const float4*)&As[kk][tm0 + 4];
            *(float4*)&b[0] = *(const float4*)&Bs[kk][tn0];
            *(float4*)&b[4] = *(const float4*)&Bs[kk][tn0 + 4];
#pragma unroll
            for (int i = 0; i < 8; i++)
#pragma unroll
                for (int j = 0; j < 8; j++)
                    acc[i][j] += a[i] * b[j];
        }
        __syncthreads();
    }
#pragma unroll
    for (int i = 0; i < 8; i++) {
        int gm = m0 + tm0 + i;
        if (gm >= M) continue;
#pragma unroll
        for (int j = 0; j < 8; j++) {
            int gn = n0 + tn0 + j;
            if (gn < N) {
                float v = acc[i][j];
                if (BIAS) v += bias[gn];
                long idx = TOUT ? (((long)(gm >> 6) * N + gn) * 64 + (gm & 63))
                                : ((long)gm * N + gn);
                C[idx] = v;
            }
        }
    }
}

// ---------------- one-time small precomputes -------------------------------
__global__ void compute_b1p(const float* __restrict__ fcb0,
                            const float* __restrict__ Wx1,
                            const float* __restrict__ brzh1,
                            float* __restrict__ out)
{
    int j = blockIdx.x * 256 + threadIdx.x;
    if (j >= G3) return;
    float s = brzh1[j];
    for (int m = 0; m < HH; m++) s += fcb0[m] * Wx1[m * G3 + j];
    out[j] = s;
}

__global__ void compute_db2(const float* __restrict__ fcb1,
                            const float* __restrict__ decW,
                            const float* __restrict__ decb,
                            float* __restrict__ out)
{
    int v = (blockIdx.x * 256 + threadIdx.x) >> 5;
    int lane = threadIdx.x & 31;
    if (v >= VV) return;
    float s = 0.f;
    for (int j = lane; j < HH; j += 32) s += fcb1[j] * decW[v * HH + j];
#pragma unroll
    for (int o = 16; o; o >>= 1) s += __shfl_xor_sync(0xffffffffu, s, o);
    if (lane == 0) out[v] = s + decb[v];
}

__global__ void init_h(const float* __restrict__ hidden)
{
    int i = blockIdx.x * 256 + threadIdx.x;
    if (i == 0) g_bar = 0;
    if (i < BB * HH) {
        int b = i >> 9, h = i & 511;
        g_h0T[h * 64 + b] = hidden[i];
        g_h1T[h * 64 + b] = hidden[BB * HH + i];
    }
}

__global__ void write_hfinal(float* __restrict__ out)
{
    int i = blockIdx.x * 256 + threadIdx.x;
    if (i < BB * HH) {
        int b = i >> 9, h = i & 511;
        out[i] = g_h0T[h * 64 + b];
        out[BB * HH + i] = g_h1T[h * 64 + b];
    }
}

// ---------------- persistent recurrent kernel ------------------------------
// Software grid barrier: cumulative counter, release via __threadfence
// (fence cumulativity covers the whole block's prior writes after the
// __syncthreads), acquire via ld.acquire.gpu poll + __syncthreads.
__device__ __forceinline__ void gridbar(unsigned target)
{
    __syncthreads();
    if (threadIdx.x == 0) {
        __threadfence();
        atomicAdd(&g_bar, 1u);
        unsigned v;
        do {
            asm volatile("ld.acquire.gpu.u32 %0, [%1];" : "=r"(v) : "l"(&g_bar));
        } while (v < target);
    }
    __syncthreads();
}

// smem layout (floats): w[36*512] | tile0[8192] | tile1[8192] |
//                       z0s[256] | z1s[256] | whxs[256] | psum[1280]
#define SM_W     0
#define SM_T0    (36*512)
#define SM_T1    (SM_T0 + 8192)
#define SM_Z0    (SM_T1 + 8192)
#define SM_Z1    (SM_Z0 + 256)
#define SM_WX    (SM_Z1 + 256)
#define SM_PS    (SM_WX + 256)
#define SM_FLOATS (SM_PS + 1280)   // 36864 floats = 147456 bytes

__global__ __launch_bounds__(512, 1)
void gru_persistent(const float* __restrict__ Uh0, const float* __restrict__ Uht0,
                    const float* __restrict__ Uh1, const float* __restrict__ Uht1)
{
    extern __shared__ float sm[];
    float* w     = sm + SM_W;
    float* tile0 = sm + SM_T0;
    float* tile1 = sm + SM_T1;
    float* z0s   = sm + SM_Z0;
    float* z1s   = sm + SM_Z1;
    float* whxs  = sm + SM_WX;
    float* psum  = sm + SM_PS;

    const int tid   = threadIdx.x;
    const int hbase = blockIdx.x * CH;

    // ---- load this block's weight slice into smem (once) ----
    // wcol order: r0(0-3) z0(4-7) uht0(8-11) m1r(12-15) m1z(16-19) m1w(20-23)
    //             u1r(24-27) u1z(28-31) uht1(32-35); each col = 512 floats.
    for (int i = tid; i < 36 * 512; i += 512) {
        int wc = i >> 9, k = i & 511, c = wc & 3;
        float v;
        if      (wc < 4)  v = Uh0[k * G2 + hbase + c];
        else if (wc < 8)  v = Uh0[k * G2 + 512 + hbase + c];
        else if (wc < 12) v = Uht0[k * HH + hbase + c];
        else if (wc < 16) v = g_M1[k * G3 + hbase + c];
        else if (wc < 20) v = g_M1[k * G3 + 512 + hbase + c];
        else if (wc < 24) v = g_M1[k * G3 + 1024 + hbase + c];
        else if (wc < 28) v = Uh1[k * G2 + hbase + c];
        else if (wc < 32) v = Uh1[k * G2 + 512 + hbase + c];
        else              v = Uht1[k * HH + hbase + c];
        w[i] = v;
    }
    __syncthreads();

    const int q = tid >> 6;          // 0..7
    const int b = tid & 63;
    const int s = tid >> 8;          // 0/1 split-k half
    const int cs = (tid >> 6) & 3;   // col for split-k stages

    unsigned bcnt = 0;

    for (int t = 0; t < TT; t++) {
        // ================= Stage A: layer0 gates r,z =================
        {
            float acc = 0.f;
            const int c = q & 3;
            for (int kc = 0; kc < 512; kc += 128) {
                for (int i = tid; i < 2048; i += 512)
                    ((float4*)tile0)[i] = __ldcg((const float4*)g_h0T + kc * 16 + i);
                __syncthreads();
                const float4* wp = (const float4*)(w + q * 512 + kc);
#pragma unroll
                for (int kl = 0; kl < 128; kl += 4) {
                    float4 wv = wp[kl >> 2];
                    acc += wv.x * tile0[kl * 64 + b] + wv.y * tile0[(kl + 1) * 64 + b]
                         + wv.z * tile0[(kl + 2) * 64 + b] + wv.w * tile0[(kl + 3) * 64 + b];
                }
                __syncthreads();
            }
            int col = hbase + c;
            float gx = g_gx0T[((long)t * G3 + (q < 4 ? 0 : 512) + col) * 64 + b];
            float v = 1.f / (1.f + expf(-(gx + acc)));
            if (q < 4) g_rh0T[col * 64 + b] = v * __ldcg(&g_h0T[col * 64 + b]);
            else       z0s[c * 64 + b] = v;
        }
        bcnt += NBLK; gridbar(bcnt);

        // ================= Stage B: update h0 =================
        {
            float acc = 0.f;
            for (int kc = 0; kc < 512; kc += 128) {
                for (int i = tid; i < 2048; i += 512)
                    ((float4*)tile0)[i] = __ldcg((const float4*)g_rh0T + kc * 16 + i);
                __syncthreads();
                if ((kc >> 8) == s) {
                    const float4* wp = (const float4*)(w + (8 + cs) * 512 + kc);
#pragma unroll
                    for (int kl = 0; kl < 128; kl += 4) {
                        float4 wv = wp[kl >> 2];
                        acc += wv.x * tile0[kl * 64 + b] + wv.y * tile0[(kl + 1) * 64 + b]
                             + wv.z * tile0[(kl + 2) * 64 + b] + wv.w * tile0[(kl + 3) * 64 + b];
                    }
                }
                __syncthreads();
            }
            if (s == 1) psum[tid & 255] = acc;
            __syncthreads();
            if (s == 0) {
                acc += psum[tid];
                int col = hbase + cs;
                float gxw = g_gx0T[((long)t * G3 + 1024 + col) * 64 + b];
                float ht = tanhf(gxw + acc);
                float z  = z0s[cs * 64 + b];
                float hp = __ldcg(&g_h0T[col * 64 + b]);
                g_h0T[col * 64 + b] = hp + z * (ht - hp);
            }
        }
        bcnt += NBLK; gridbar(bcnt);

        // ================= Stage C: layer1 gates =================
        {
            float a0 = 0.f, a1 = 0.f, a2 = 0.f;
            const int c = q & 3;
            for (int kc = 0; kc < 512; kc += 128) {
                for (int i = tid; i < 4096; i += 512) {
                    if (i < 2048)
                        ((float4*)tile0)[i] = __ldcg((const float4*)g_h0T + kc * 16 + i);
                    else
                        ((float4*)tile1)[i - 2048] = __ldcg((const float4*)g_h1T + kc * 16 + (i - 2048));
                }
                __syncthreads();
                if (q < 4) {
                    const float4* wr = (const float4*)(w + (12 + c) * 512 + kc);
                    const float4* wz = (const float4*)(w + (16 + c) * 512 + kc);
                    const float4* ww = (const float4*)(w + (20 + c) * 512 + kc);
#pragma unroll
                    for (int kl = 0; kl < 128; kl += 4) {
                        float t0 = tile0[kl * 64 + b], t1 = tile0[(kl + 1) * 64 + b];
                        float t2 = tile0[(kl + 2) * 64 + b], t3 = tile0[(kl + 3) * 64 + b];
                        float4 vr = wr[kl >> 2], vz = wz[kl >> 2], vw = ww[kl >> 2];
                        a0 += vr.x * t0 + vr.y * t1 + vr.z * t2 + vr.w * t3;
                        a1 += vz.x * t0 + vz.y * t1 + vz.z * t2 + vz.w * t3;
                        a2 += vw.x * t0 + vw.y * t1 + vw.z * t2 + vw.w * t3;
                    }
                } else {
                    const float4* wr = (const float4*)(w + (24 + c) * 512 + kc);
                    const float4* wz = (const float4*)(w + (28 + c) * 512 + kc);
#pragma unroll
                    for (int kl = 0; kl < 128; kl += 4) {
                        float t0 = tile1[kl * 64 + b], t1 = tile1[(kl + 1) * 64 + b];
                        float t2 = tile1[(kl + 2) * 64 + b], t3 = tile1[(kl + 3) * 64 + b];
                        float4 vr = wr[kl >> 2], vz = wz[kl >> 2];
                        a0 += vr.x * t0 + vr.y * t1 + vr.z * t2 + vr.w * t3;
                        a1 += vz.x * t0 + vz.y * t1 + vz.z * t2 + vz.w * t3;
                    }
                }
                __syncthreads();
            }
            int o = c * 64 + b;
            if (q < 4) { psum[o] = a0; psum[256 + o] = a1; psum[512 + o] = a2; }
            else       { psum[768 + o] = a0; psum[1024 + o] = a1; }
            __syncthreads();
            if (tid < 256) {
                int c2 = tid >> 6, b2 = tid & 63, col = hbase + c2;
                float r1 = 1.f / (1.f + expf(-(psum[tid] + psum[768 + tid] + g_b1p[col])));
                float z1 = 1.f / (1.f + expf(-(psum[256 + tid] + psum[1024 + tid] + g_b1p[512 + col])));
                float wx = psum[512 + tid] + g_b1p[1024 + col];
                float h1v = __ldcg(&g_h1T[col * 64 + b2]);
                g_rh1T[col * 64 + b2] = r1 * h1v;
                z1s[tid] = z1;
                whxs[tid] = wx;
            }
        }
        bcnt += NBLK; gridbar(bcnt);

        // ================= Stage D: update h1, emit Hseq =================
        {
            float acc = 0.f;
            for (int kc = 0; kc < 512; kc += 128) {
                for (int i = tid; i < 2048; i += 512)
                    ((float4*)tile0)[i] = __ldcg((const float4*)g_rh1T + kc * 16 + i);
                __syncthreads();
                if ((kc >> 8) == s) {
                    const float4* wp = (const float4*)(w + (32 + cs) * 512 + kc);
#pragma unroll
                    for (int kl = 0; kl < 128; kl += 4) {
                        float4 wv = wp[kl >> 2];
                        acc += wv.x * tile0[kl * 64 + b] + wv.y * tile0[(kl + 1) * 64 + b]
                             + wv.z * tile0[(kl + 2) * 64 + b] + wv.w * tile0[(kl + 3) * 64 + b];
                    }
                }
                __syncthreads();
            }
            if (s == 1) psum[tid & 255] = acc;
            __syncthreads();
            if (s == 0) {
                acc += psum[tid];
                int col = hbase + cs;
                float ht = tanhf(whxs[tid] + acc);
                float z  = z1s[tid];
                float hp = __ldcg(&g_h1T[col * 64 + b]);
                float hn = hp + z * (ht - hp);
                g_h1T[col * 64 + b] = hn;
                g_Hseq[((long)t * 64 + b) * 512 + col] = hn;
            }
        }
        bcnt += NBLK; gridbar(bcnt);
    }
}

// ---------------- host launch ----------------------------------------------
extern "C" void kernel_launch(void* const* d_in, const int* in_sizes, int n_in,
                              void* d_out, int out_size)
{
    const int*   inputs = (const int*)  d_in[0];            // (T,B)
    const float* hidden = (const float*)d_in[1];            // (2,B,H)
    const float* embt   = (const float*)d_in[2];            // (V,E)
    const float* W_x    = (const float*)d_in[3];            // (2,H,3H)
    const float* U_h    = (const float*)d_in[4];            // (2,H,2H)
    const float* U_ht   = (const float*)d_in[5];            // (2,H,H)
    const float* b_rzh  = (const float*)d_in[6];            // (2,3H)
    const float* fc_W   = (const float*)d_in[7];            // (2,H,H)
    const float* fc_b   = (const float*)d_in[8];            // (2,H)
    const float* dec_W  = (const float*)d_in[9];            // (V,H)
    const float* dec_b  = (const float*)d_in[10];           // (V,)
    float* out = (float*)d_out;

    const float* W_x0  = W_x;
    const float* W_x1  = W_x + HH * G3;
    const float* U_h0  = U_h;
    const float* U_h1  = U_h + HH * G2;
    const float* U_ht0 = U_ht;
    const float* U_ht1 = U_ht + HH * HH;
    const float* fc0   = fc_W;
    const float* fc1   = fc_W + HH * HH;

    float* pGX0 = nullptr; cudaGetSymbolAddress((void**)&pGX0, g_gx0T);
    float* pM1  = nullptr; cudaGetSymbolAddress((void**)&pM1,  g_M1);
    float* pB1p = nullptr; cudaGetSymbolAddress((void**)&pB1p, g_b1p);
    float* pDmt = nullptr; cudaGetSymbolAddress((void**)&pDmt, g_Dmt);
    float* pDb2 = nullptr; cudaGetSymbolAddress((void**)&pDb2, g_db2);
    float* pHsq = nullptr; cudaGetSymbolAddress((void**)&pHsq, g_Hseq);

    static bool attr_set = false;
    if (!attr_set) {
        cudaFuncSetAttribute(gru_persistent,
                             cudaFuncAttributeMaxDynamicSharedMemorySize,
                             SM_FLOATS * sizeof(float));
        attr_set = true;
    }

    // 0) init h (transposed) + grid-barrier counter
    init_h<<<(BB * HH + 255) / 256, 256>>>(hidden);

    // 1) GX0^T = (gather(emb) @ W_x0 + b_rzh0) transposed to [t][col][b]
    gemm128<0, 0, true, true, true><<<dim3(G3 / 128, MB / 128), 256>>>(
        embt, W_x0, b_rzh, inputs, pGX0, MB, G3, HH);

    // 2) M1 = fc0^T @ W_x1, b1' = fc_b0 @ W_x1 + b_rzh1
    gemm128<1, 0, false, false, false><<<dim3(G3 / 128, HH / 128), 256>>>(
        fc0, W_x1, nullptr, nullptr, pM1, HH, G3, HH);
    compute_b1p<<<(G3 + 255) / 256, 256>>>(fc_b, W_x1, b_rzh + G3, pB1p);

    // 3) Dmt = dec_W @ fc1  (V x H), db2 = dec_W @ fc_b1 + dec_b
    gemm128<0, 0, false, false, false><<<dim3(HH / 128, (VV + 127) / 128), 256>>>(
        dec_W, fc1, nullptr, nullptr, pDmt, VV, HH, HH);
    compute_db2<<<(VV * 32 + 255) / 256, 256>>>(fc_b + HH, dec_W, dec_b, pDb2);

    // 4) entire 128-step recurrence in ONE persistent kernel
    gru_persistent<<<NBLK, 512, SM_FLOATS * sizeof(float)>>>(
        U_h0, U_ht0, U_h1, U_ht1);

    // 5) logits = Hseq[8192 x 512] @ Dmt^T[512 x 10000] + db2
    gemm128<0, 1, false, true, false><<<dim3((VV + 127) / 128, MB / 128), 256>>>(
        pHsq, pDmt, pDb2, nullptr, out, MB, VV, HH);

    // 6) h_final appended after logits (if harness expects it)
    if (out_size >= (long)MB * VV + 2 * BB * HH) {
        write_hfinal<<<(BB * HH + 255) / 256, 256>>>(out + (long)MB * VV);
    }
}

// round 9
// speedup vs baseline: 3.3874x; 1.1592x over previous
#include <cuda_runtime.h>
#include <cuda_bf16.h>
#include <math.h>

// Problem constants
#define TT   128
#define BB   64
#define HH   512
#define VV   10000
#define G3   1536   // 3*H
#define G2   1024   // 2*H
#define MB   (TT*BB)   // 8192 rows
#define NBLK 128       // persistent blocks
#define CH   4         // h-columns owned per block
#define NCTR 8         // distributed barrier counters

typedef unsigned long long ull;

// ---------------- f32x2 packed-FMA helpers (Blackwell FFMA2) ---------------
__device__ __forceinline__ ull pack2(float x, float y) {
    ull r; asm("mov.b64 %0, {%1, %2};" : "=l"(r) : "f"(x), "f"(y)); return r;
}
__device__ __forceinline__ void ffma2(ull& d, ull a, ull b) {
    asm("fma.rn.f32x2 %0, %1, %2, %0;" : "+l"(d) : "l"(a), "l"(b));
}
__device__ __forceinline__ float2 unpack2(ull v) {
    float2 f; asm("mov.b64 {%0, %1}, %2;" : "=f"(f.x), "=f"(f.y) : "l"(v)); return f;
}

// ---------------- device scratch (static: no allocations allowed) ----------
__device__ unsigned g_ctr[NCTR*64];        // barrier counters, 256B apart
__device__ float g_h0T[HH*BB];             // transposed activations [h][b]
__device__ float g_h1T[HH*BB];
__device__ float g_rh0T[HH*BB];
__device__ float g_rh1T[HH*BB];
__device__ float g_gx0T[(long)MB*G3];      // [t][col][b]
__device__ float g_M1[HH*G3];              // fc0^T @ W_x1
__device__ float g_b1p[G3];
__device__ float g_Dmt[(long)VV*HH];       // dec_W @ fc1  (V x H)
__device__ float g_db2[VV];
__device__ float g_Hseq[(long)MB*HH];      // h1 per step, [t][b][h]

// ---------------- generic tiled GEMM 128x128x16 (FFMA2 inner) --------------
template<int OPA, int OPB, bool GATHER, bool BIAS, bool TOUT>
__global__ __launch_bounds__(256, 1)
void gemm128(const float* __restrict__ A, const float* __restrict__ B,
             const float* __restrict__ bias, const int* __restrict__ gidx,
             float* __restrict__ C, int M, int N, int K)
{
    const int BM = 128, BN = 128, BK = 16;
    __shared__ float As[BK][BM];
    __shared__ float Bs[BK][BN];
    const int m0 = blockIdx.y * BM;
    const int n0 = blockIdx.x * BN;
    const int tid = threadIdx.x;
    const int tm0 = (tid & 15) * 8;
    const int tn0 = (tid >> 4) * 8;
    ull acc[8][4];
#pragma unroll
    for (int i = 0; i < 8; i++)
#pragma unroll
        for (int j = 0; j < 4; j++) acc[i][j] = 0ULL;

    for (int k0 = 0; k0 < K; k0 += BK) {
        if (OPA == 0) {
            int kk = tid & 15, mr = tid >> 4;
#pragma unroll
            for (int i = 0; i < 8; i++) {
                int m = mr + i * 16;
                int gm = m0 + m;
                float v = 0.f;
                if (gm < M) {
                    long row = GATHER ? (long)gidx[gm] : (long)gm;
                    v = A[row * K + k0 + kk];
                }
                As[kk][m] = v;
            }
        } else {
            int m = tid & 127, kb = tid >> 7;
#pragma unroll
            for (int i = 0; i < 8; i++) {
                int kk = kb + i * 2;
                int gm = m0 + m;
                As[kk][m] = (gm < M) ? A[(long)(k0 + kk) * M + gm] : 0.f;
            }
        }
        if (OPB == 0) {
            int n = tid & 127, kb = tid >> 7;
#pragma unroll
            for (int i = 0; i < 8; i++) {
                int kk = kb + i * 2;
                int gn = n0 + n;
                Bs[kk][n] = (gn < N) ? B[(long)(k0 + kk) * N + gn] : 0.f;
            }
        } else {
            int kk = tid & 15, nr = tid >> 4;
#pragma unroll
            for (int i = 0; i < 8; i++) {
                int n = nr + i * 16;
                int gn = n0 + n;
                Bs[kk][n] = (gn < N) ? B[(long)gn * K + k0 + kk] : 0.f;
            }
        }
        __syncthreads();
#pragma unroll
        for (int kk = 0; kk < BK; kk++) {
            float a[8];
            *(float4*)&a[0] = *(const float4*)&As[kk][tm0];
            *(float4*)&a[4] = *(const float4*)&As[kk][tm0 + 4];
            ull b2[4];
            *(ulonglong2*)&b2[0] = *(const ulonglong2*)&Bs[kk][tn0];
            *(ulonglong2*)&b2[2] = *(const ulonglong2*)&Bs[kk][tn0 + 4];
#pragma unroll
            for (int i = 0; i < 8; i++) {
                ull ai = pack2(a[i], a[i]);
#pragma unroll
                for (int j = 0; j < 4; j++) ffma2(acc[i][j], ai, b2[j]);
            }
        }
        __syncthreads();
    }
#pragma unroll
    for (int i = 0; i < 8; i++) {
        int gm = m0 + tm0 + i;
        if (gm >= M) continue;
#pragma unroll
        for (int j2 = 0; j2 < 4; j2++) {
            float2 f = unpack2(acc[i][j2]);
#pragma unroll
            for (int u = 0; u < 2; u++) {
                int gn = n0 + tn0 + j2 * 2 + u;
                if (gn < N) {
                    float v = (u == 0) ? f.x : f.y;
                    if (BIAS) v += bias[gn];
                    long idx = TOUT ? (((long)(gm >> 6) * N + gn) * 64 + (gm & 63))
                                    : ((long)gm * N + gn);
                    C[idx] = v;
                }
            }
        }
    }
}

// ---------------- one-time small precomputes -------------------------------
__global__ void compute_b1p(const float* __restrict__ fcb0,
                            const float* __restrict__ Wx1,
                            const float* __restrict__ brzh1,
                            float* __restrict__ out)
{
    int j = blockIdx.x * 256 + threadIdx.x;
    if (j >= G3) return;
    float s = brzh1[j];
#pragma unroll 16
    for (int m = 0; m < HH; m++) s += __ldg(&fcb0[m]) * __ldg(&Wx1[m * G3 + j]);
    out[j] = s;
}

__global__ void compute_db2(const float* __restrict__ fcb1,
                            const float* __restrict__ decW,
                            const float* __restrict__ decb,
                            float* __restrict__ out)
{
    int v = (blockIdx.x * 256 + threadIdx.x) >> 5;
    int lane = threadIdx.x & 31;
    if (v >= VV) return;
    float s = 0.f;
    for (int j = lane; j < HH; j += 32) s += fcb1[j] * decW[v * HH + j];
#pragma unroll
    for (int o = 16; o; o >>= 1) s += __shfl_xor_sync(0xffffffffu, s, o);
    if (lane == 0) out[v] = s + decb[v];
}

__global__ void init_h(const float* __restrict__ hidden)
{
    int i = blockIdx.x * 256 + threadIdx.x;
    if (i < NCTR * 64) g_ctr[i] = 0u;
    if (i < BB * HH) {
        int b = i >> 9, h = i & 511;
        g_h0T[h * 64 + b] = hidden[i];
        g_h1T[h * 64 + b] = hidden[BB * HH + i];
    }
}

__global__ void write_hfinal(float* __restrict__ out)
{
    int i = blockIdx.x * 256 + threadIdx.x;
    if (i < BB * HH) {
        int b = i >> 9, h = i & 511;
        out[i] = g_h0T[h * 64 + b];
        out[BB * HH + i] = g_h1T[h * 64 + b];
    }
}

// ---------------- distributed grid barrier ---------------------------------
__device__ __forceinline__ void gridbar(unsigned target)
{
    __syncthreads();
    if (threadIdx.x == 0) {
        unsigned* my = &g_ctr[(blockIdx.x & (NCTR - 1)) * 64];
        asm volatile("red.release.gpu.global.add.u32 [%0], 1;" :: "l"(my) : "memory");
        unsigned s;
        do {
            s = 0;
#pragma unroll
            for (int i = 0; i < NCTR; i++) {
                unsigned v;
                asm volatile("ld.acquire.gpu.global.u32 %0, [%1];"
                             : "=r"(v) : "l"(&g_ctr[i * 64]) : "memory");
                s += v;
            }
        } while (s < target);
    }
    __syncthreads();
}

// smem layout (floats):
//   w[9*512*4] | bufs[2*8192] | ps[10240] | z0s[256] | z1s[256] | whxs[256]
#define SM_W   0
#define SM_BUF 18432
#define SM_PS  34816
#define SM_Z0  45056
#define SM_Z1  45312
#define SM_WX  45568
#define SM_FLOATS 45824   // 183296 bytes

// ---------------- persistent recurrent kernel ------------------------------
__global__ __launch_bounds__(512, 1)
void gru_persistent(const float* __restrict__ Uh0, const float* __restrict__ Uht0,
                    const float* __restrict__ Uh1, const float* __restrict__ Uht1)
{
    extern __shared__ float sm[];
    float* w    = sm + SM_W;     // [g][k][4c], g: 0=r0 1=z0 2=uht0 3=m1r 4=m1z 5=m1w 6=u1r 7=u1z 8=uht1
    float* bufs = sm + SM_BUF;
    float* ps   = sm + SM_PS;
    float* z0s  = sm + SM_Z0;
    float* z1s  = sm + SM_Z1;
    float* whxs = sm + SM_WX;

    const int tid   = threadIdx.x;
    const int hbase = blockIdx.x * CH;

    // ---- stage weights into smem once ----
    for (int i = tid; i < 9 * 512 * 4; i += 512) {
        int c = i & 3, k = (i >> 2) & 511, g = i >> 11;
        float v;
        switch (g) {
            case 0:  v = Uh0[k * G2 + hbase + c]; break;
            case 1:  v = Uh0[k * G2 + 512 + hbase + c]; break;
            case 2:  v = Uht0[k * HH + hbase + c]; break;
            case 3:  v = g_M1[k * G3 + hbase + c]; break;
            case 4:  v = g_M1[k * G3 + 512 + hbase + c]; break;
            case 5:  v = g_M1[k * G3 + 1024 + hbase + c]; break;
            case 6:  v = Uh1[k * G2 + hbase + c]; break;
            case 7:  v = Uh1[k * G2 + 512 + hbase + c]; break;
            default: v = Uht1[k * HH + hbase + c]; break;
        }
        w[i] = v;
    }
    __syncthreads();

    const int b  = tid & 63;     // batch lane
    const int ks = tid >> 6;     // 0..7 k-split
    // reducer-role indices
    const int rb  = tid & 63;
    const int rc4 = tid >> 7;           // 0..3  (stage A: col within quad)
    const int rcq = (tid >> 6) & 1;     // stage A: gate (0=r,1=z)
    const int rc2 = (tid >> 6) & 3;     // stages B/C/D (tid<256): col
    unsigned bcnt = 0;

    for (int t = 0; t < TT; t++) {
        // =============== Stage A: layer0 gates r,z ===============
        {
            // prefetch epilogue operand early
            float gx_pre = __ldg(&g_gx0T[((long)t * G3 + rcq * 512 + hbase + rc4) * 64 + rb]);
            ull ar0 = 0, ar1 = 0, az0 = 0, az1 = 0;
            const float4* src = (const float4*)g_h0T;
            float4 r0 = __ldcg(src + tid), r1 = __ldcg(src + 512 + tid),
                   r2 = __ldcg(src + 1024 + tid), r3 = __ldcg(src + 1536 + tid);
#pragma unroll
            for (int ph = 0; ph < 4; ph++) {
                float* bp = bufs + (ph & 1) * 8192;
                ((float4*)bp)[tid] = r0; ((float4*)bp)[512 + tid] = r1;
                ((float4*)bp)[1024 + tid] = r2; ((float4*)bp)[1536 + tid] = r3;
                __syncthreads();
                if (ph < 3) {
                    const float4* s2 = src + (ph + 1) * 2048;
                    r0 = __ldcg(s2 + tid); r1 = __ldcg(s2 + 512 + tid);
                    r2 = __ldcg(s2 + 1024 + tid); r3 = __ldcg(s2 + 1536 + tid);
                }
                const float* ap = bp + (ks * 16) * 64 + b;
                const float* wr = w + (0 * 512 + ph * 128 + ks * 16) * 4;
                const float* wz = w + (1 * 512 + ph * 128 + ks * 16) * 4;
#pragma unroll
                for (int j = 0; j < 16; j++) {
                    float a = ap[j * 64];
                    ull a2 = pack2(a, a);
                    ulonglong2 vr = *(const ulonglong2*)(wr + j * 4);
                    ulonglong2 vz = *(const ulonglong2*)(wz + j * 4);
                    ffma2(ar0, a2, vr.x); ffma2(ar1, a2, vr.y);
                    ffma2(az0, a2, vz.x); ffma2(az1, a2, vz.y);
                }
            }
            {   // psum group (ks*2+gg), layout (group)*256 + c*64 + b
                float2 f;
                float* pr = ps + (ks * 2 + 0) * 256 + b;
                f = unpack2(ar0); pr[0] = f.x; pr[64] = f.y;
                f = unpack2(ar1); pr[128] = f.x; pr[192] = f.y;
                float* pz = ps + (ks * 2 + 1) * 256 + b;
                f = unpack2(az0); pz[0] = f.x; pz[64] = f.y;
                f = unpack2(az1); pz[128] = f.x; pz[192] = f.y;
            }
            __syncthreads();
            {
                // FIXED reduction: sum groups (ks2*2 + rcq) for ks2 = 0..7
                float v = 0.f;
#pragma unroll
                for (int ks2 = 0; ks2 < 8; ks2++)
                    v += ps[((ks2 * 2 + rcq) * 4 + rc4) * 64 + rb];
                int col = hbase + rc4;
                float sg = 1.f / (1.f + expf(-(gx_pre + v)));
                if (rcq == 0) g_rh0T[col * 64 + rb] = sg * __ldcg(&g_h0T[col * 64 + rb]);
                else          z0s[rc4 * 64 + rb] = sg;
            }
        }
        bcnt += NBLK; gridbar(bcnt);

        // =============== Stage B: update h0 ===============
        {
            float gxw_pre = (tid < 256)
                ? __ldg(&g_gx0T[((long)t * G3 + 1024 + hbase + rc2) * 64 + rb]) : 0.f;
            ull a0 = 0, a1 = 0;
            const float4* src = (const float4*)g_rh0T;
            float4 r0 = __ldcg(src + tid), r1 = __ldcg(src + 512 + tid),
                   r2 = __ldcg(src + 1024 + tid), r3 = __ldcg(src + 1536 + tid);
#pragma unroll
            for (int ph = 0; ph < 4; ph++) {
                float* bp = bufs + (ph & 1) * 8192;
                ((float4*)bp)[tid] = r0; ((float4*)bp)[512 + tid] = r1;
                ((float4*)bp)[1024 + tid] = r2; ((float4*)bp)[1536 + tid] = r3;
                __syncthreads();
                if (ph < 3) {
                    const float4* s2 = src + (ph + 1) * 2048;
                    r0 = __ldcg(s2 + tid); r1 = __ldcg(s2 + 512 + tid);
                    r2 = __ldcg(s2 + 1024 + tid); r3 = __ldcg(s2 + 1536 + tid);
                }
                const float* ap = bp + (ks * 16) * 64 + b;
                const float* wp = w + (2 * 512 + ph * 128 + ks * 16) * 4;
#pragma unroll
                for (int j = 0; j < 16; j++) {
                    float a = ap[j * 64];
                    ull a2 = pack2(a, a);
                    ulonglong2 wv = *(const ulonglong2*)(wp + j * 4);
                    ffma2(a0, a2, wv.x); ffma2(a1, a2, wv.y);
                }
            }
            {
                float2 f;
                float* pp = ps + ks * 256 + b;
                f = unpack2(a0); pp[0] = f.x; pp[64] = f.y;
                f = unpack2(a1); pp[128] = f.x; pp[192] = f.y;
            }
            __syncthreads();
            if (tid < 256) {
                float v = 0.f;
#pragma unroll
                for (int k2 = 0; k2 < 8; k2++) v += ps[(k2 * 4 + rc2) * 64 + rb];
                int col = hbase + rc2;
                float ht = tanhf(gxw_pre + v);
                float z  = z0s[rc2 * 64 + rb];
                float hp = __ldcg(&g_h0T[col * 64 + rb]);
                g_h0T[col * 64 + rb] = hp + z * (ht - hp);
            }
        }
        bcnt += NBLK; gridbar(bcnt);

        // =============== Stage C: layer1 gates ===============
        {
            ull mr0 = 0, mr1 = 0, mz0 = 0, mz1 = 0, mw0 = 0, mw1 = 0; // from h0_new
            ull ur0 = 0, ur1 = 0, uz0 = 0, uz1 = 0;                    // from h1
            const float4* s0 = (const float4*)g_h0T;
            const float4* s1 = (const float4*)g_h1T;
            float4 r0 = __ldcg(s0 + tid), r1 = __ldcg(s0 + 512 + tid),
                   r2 = __ldcg(s0 + 1024 + tid), r3 = __ldcg(s0 + 1536 + tid);
#pragma unroll
            for (int ph = 0; ph < 8; ph++) {
                float* bp = bufs + (ph & 1) * 8192;
                ((float4*)bp)[tid] = r0; ((float4*)bp)[512 + tid] = r1;
                ((float4*)bp)[1024 + tid] = r2; ((float4*)bp)[1536 + tid] = r3;
                __syncthreads();
                if (ph < 7) {
                    const float4* sn = (ph + 1 < 4) ? s0 : s1;
                    const float4* s2 = sn + ((ph + 1) & 3) * 2048;
                    r0 = __ldcg(s2 + tid); r1 = __ldcg(s2 + 512 + tid);
                    r2 = __ldcg(s2 + 1024 + tid); r3 = __ldcg(s2 + 1536 + tid);
                }
                const float* ap = bp + (ks * 16) * 64 + b;
                const int kk = ((ph & 3) * 128 + ks * 16) * 4;
                if (ph < 4) {
                    const float* w3 = w + (3 * 512) * 4 + kk;
                    const float* w4 = w + (4 * 512) * 4 + kk;
                    const float* w5 = w + (5 * 512) * 4 + kk;
#pragma unroll
                    for (int j = 0; j < 16; j++) {
                        float a = ap[j * 64];
                        ull a2 = pack2(a, a);
                        ulonglong2 v3 = *(const ulonglong2*)(w3 + j * 4);
                        ulonglong2 v4 = *(const ulonglong2*)(w4 + j * 4);
                        ulonglong2 v5 = *(const ulonglong2*)(w5 + j * 4);
                        ffma2(mr0, a2, v3.x); ffma2(mr1, a2, v3.y);
                        ffma2(mz0, a2, v4.x); ffma2(mz1, a2, v4.y);
                        ffma2(mw0, a2, v5.x); ffma2(mw1, a2, v5.y);
                    }
                } else {
                    const float* w6 = w + (6 * 512) * 4 + kk;
                    const float* w7 = w + (7 * 512) * 4 + kk;
#pragma unroll
                    for (int j = 0; j < 16; j++) {
                        float a = ap[j * 64];
                        ull a2 = pack2(a, a);
                        ulonglong2 v6 = *(const ulonglong2*)(w6 + j * 4);
                        ulonglong2 v7 = *(const ulonglong2*)(w7 + j * 4);
                        ffma2(ur0, a2, v6.x); ffma2(ur1, a2, v6.y);
                        ffma2(uz0, a2, v7.x); ffma2(uz1, a2, v7.y);
                    }
                }
            }
            {   // psum: group (ks*5+gg), gg: 0 r_h0, 1 z_h0, 2 w_h0, 3 r_h1, 4 z_h1
                float2 f;
                float* p0 = ps + (ks * 5 + 0) * 256 + b;
                f = unpack2(mr0); p0[0] = f.x; p0[64] = f.y;
                f = unpack2(mr1); p0[128] = f.x; p0[192] = f.y;
                float* p1 = ps + (ks * 5 + 1) * 256 + b;
                f = unpack2(mz0); p1[0] = f.x; p1[64] = f.y;
                f = unpack2(mz1); p1[128] = f.x; p1[192] = f.y;
                float* p2 = ps + (ks * 5 + 2) * 256 + b;
                f = unpack2(mw0); p2[0] = f.x; p2[64] = f.y;
                f = unpack2(mw1); p2[128] = f.x; p2[192] = f.y;
                float* p3 = ps + (ks * 5 + 3) * 256 + b;
                f = unpack2(ur0); p3[0] = f.x; p3[64] = f.y;
                f = unpack2(ur1); p3[128] = f.x; p3[192] = f.y;
                float* p4 = ps + (ks * 5 + 4) * 256 + b;
                f = unpack2(uz0); p4[0] = f.x; p4[64] = f.y;
                f = unpack2(uz1); p4[128] = f.x; p4[192] = f.y;
            }
            __syncthreads();
            if (tid < 256) {
                float sr = 0.f, sz = 0.f, sw = 0.f;
#pragma unroll
                for (int k2 = 0; k2 < 8; k2++) {
                    int base = k2 * 5 * 256 + rc2 * 64 + rb;
                    sr += ps[base]           + ps[base + 3 * 256];
                    sz += ps[base + 256]     + ps[base + 4 * 256];
                    sw += ps[base + 2 * 256];
                }
                int col = hbase + rc2;
                float r1v = 1.f / (1.f + expf(-(sr + __ldg(&g_b1p[col]))));
                float z1v = 1.f / (1.f + expf(-(sz + __ldg(&g_b1p[512 + col]))));
                float wx  = sw + __ldg(&g_b1p[1024 + col]);
                float h1v = __ldcg(&g_h1T[col * 64 + rb]);
                g_rh1T[col * 64 + rb] = r1v * h1v;
                z1s[tid]  = z1v;
                whxs[tid] = wx;
            }
        }
        bcnt += NBLK; gridbar(bcnt);

        // =============== Stage D: update h1, emit Hseq ===============
        {
            ull a0 = 0, a1 = 0;
            const float4* src = (const float4*)g_rh1T;
            float4 r0 = __ldcg(src + tid), r1 = __ldcg(src + 512 + tid),
                   r2 = __ldcg(src + 1024 + tid), r3 = __ldcg(src + 1536 + tid);
#pragma unroll
            for (int ph = 0; ph < 4; ph++) {
                float* bp = bufs + (ph & 1) * 8192;
                ((float4*)bp)[tid] = r0; ((float4*)bp)[512 + tid] = r1;
                ((float4*)bp)[1024 + tid] = r2; ((float4*)bp)[1536 + tid] = r3;
                __syncthreads();
                if (ph < 3) {
                    const float4* s2 = src + (ph + 1) * 2048;
                    r0 = __ldcg(s2 + tid); r1 = __ldcg(s2 + 512 + tid);
                    r2 = __ldcg(s2 + 1024 + tid); r3 = __ldcg(s2 + 1536 + tid);
                }
                const float* ap = bp + (ks * 16) * 64 + b;
                const float* wp = w + (8 * 512 + ph * 128 + ks * 16) * 4;
#pragma unroll
                for (int j = 0; j < 16; j++) {
                    float a = ap[j * 64];
                    ull a2 = pack2(a, a);
                    ulonglong2 wv = *(const ulonglong2*)(wp + j * 4);
                    ffma2(a0, a2, wv.x); ffma2(a1, a2, wv.y);
                }
            }
            {
                float2 f;
                float* pp = ps + ks * 256 + b;
                f = unpack2(a0); pp[0] = f.x; pp[64] = f.y;
                f = unpack2(a1); pp[128] = f.x; pp[192] = f.y;
            }
            __syncthreads();
            if (tid < 256) {
                float v = 0.f;
#pragma unroll
                for (int k2 = 0; k2 < 8; k2++) v += ps[(k2 * 4 + rc2) * 64 + rb];
                int col = hbase + rc2;
                float ht = tanhf(whxs[tid] + v);
                float z  = z1s[tid];
                float hp = __ldcg(&g_h1T[col * 64 + rb]);
                float hn = hp + z * (ht - hp);
                g_h1T[col * 64 + rb] = hn;
                g_Hseq[((long)t * 64 + rb) * 512 + col] = hn;
            }
        }
        bcnt += NBLK; gridbar(bcnt);
    }
}

// ---------------- host launch ----------------------------------------------
extern "C" void kernel_launch(void* const* d_in, const int* in_sizes, int n_in,
                              void* d_out, int out_size)
{
    const int*   inputs = (const int*)  d_in[0];            // (T,B)
    const float* hidden = (const float*)d_in[1];            // (2,B,H)
    const float* embt   = (const float*)d_in[2];            // (V,E)
    const float* W_x    = (const float*)d_in[3];            // (2,H,3H)
    const float* U_h    = (const float*)d_in[4];            // (2,H,2H)
    const float* U_ht   = (const float*)d_in[5];            // (2,H,H)
    const float* b_rzh  = (const float*)d_in[6];            // (2,3H)
    const float* fc_W   = (const float*)d_in[7];            // (2,H,H)
    const float* fc_b   = (const float*)d_in[8];            // (2,H)
    const float* dec_W  = (const float*)d_in[9];            // (V,H)
    const float* dec_b  = (const float*)d_in[10];           // (V,)
    float* out = (float*)d_out;

    const float* W_x0  = W_x;
    const float* W_x1  = W_x + HH * G3;
    const float* U_h0  = U_h;
    const float* U_h1  = U_h + HH * G2;
    const float* U_ht0 = U_ht;
    const float* U_ht1 = U_ht + HH * HH;
    const float* fc0   = fc_W;
    const float* fc1   = fc_W + HH * HH;

    float* pGX0 = nullptr; cudaGetSymbolAddress((void**)&pGX0, g_gx0T);
    float* pM1  = nullptr; cudaGetSymbolAddress((void**)&pM1,  g_M1);
    float* pB1p = nullptr; cudaGetSymbolAddress((void**)&pB1p, g_b1p);
    float* pDmt = nullptr; cudaGetSymbolAddress((void**)&pDmt, g_Dmt);
    float* pDb2 = nullptr; cudaGetSymbolAddress((void**)&pDb2, g_db2);
    float* pHsq = nullptr; cudaGetSymbolAddress((void**)&pHsq, g_Hseq);

    static bool attr_set = false;
    if (!attr_set) {
        cudaFuncSetAttribute(gru_persistent,
                             cudaFuncAttributeMaxDynamicSharedMemorySize,
                             SM_FLOATS * sizeof(float));
        attr_set = true;
    }

    // 0) init h (transposed) + barrier counters
    init_h<<<(BB * HH + 255) / 256, 256>>>(hidden);

    // 1) GX0^T = (gather(emb) @ W_x0 + b_rzh0) -> [t][col][b]
    gemm128<0, 0, true, true, true><<<dim3(G3 / 128, MB / 128), 256>>>(
        embt, W_x0, b_rzh, inputs, pGX0, MB, G3, HH);

    // 2) M1 = fc0^T @ W_x1, b1' = fc_b0 @ W_x1 + b_rzh1
    gemm128<1, 0, false, false, false><<<dim3(G3 / 128, HH / 128), 256>>>(
        fc0, W_x1, nullptr, nullptr, pM1, HH, G3, HH);
    compute_b1p<<<(G3 + 255) / 256, 256>>>(fc_b, W_x1, b_rzh + G3, pB1p);

    // 3) Dmt = dec_W @ fc1  (V x H), db2 = dec_W @ fc_b1 + dec_b
    gemm128<0, 0, false, false, false><<<dim3(HH / 128, (VV + 127) / 128), 256>>>(
        dec_W, fc1, nullptr, nullptr, pDmt, VV, HH, HH);
    compute_db2<<<(VV * 32 + 255) / 256, 256>>>(fc_b + HH, dec_W, dec_b, pDb2);

    // 4) entire 128-step recurrence in ONE persistent kernel
    gru_persistent<<<NBLK, 512, SM_FLOATS * sizeof(float)>>>(
        U_h0, U_ht0, U_h1, U_ht1);

    // 5) logits = Hseq[8192 x 512] @ Dmt^T + db2
    gemm128<0, 1, false, true, false><<<dim3((VV + 127) / 128, MB / 128), 256>>>(
        pHsq, pDmt, pDb2, nullptr, out, MB, VV, HH);

    // 6) h_final appended after logits (if harness expects it)
    if (out_size >= (long)MB * VV + 2 * BB * HH) {
        write_hfinal<<<(BB * HH + 255) / 256, 256>>>(out + (long)MB * VV);
    }
}

// round 10
// speedup vs baseline: 4.1723x; 1.2317x over previous
#include <cuda_runtime.h>
#include <cuda_bf16.h>
#include <math.h>

// Problem constants
#define TT   128
#define BB   64
#define HH   512
#define VV   10000
#define G3   1536   // 3*H
#define G2   1024   // 2*H
#define MB   (TT*BB)   // 8192 rows
#define NBLK 128       // persistent blocks
#define CH   4         // h-columns owned per block

typedef unsigned long long ull;

// ---------------- f32x2 packed-FMA helpers (Blackwell FFMA2) ---------------
__device__ __forceinline__ ull pack2(float x, float y) {
    ull r; asm("mov.b64 %0, {%1, %2};" : "=l"(r) : "f"(x), "f"(y)); return r;
}
__device__ __forceinline__ void ffma2(ull& d, ull a, ull b) {
    asm("fma.rn.f32x2 %0, %1, %2, %0;" : "+l"(d) : "l"(a), "l"(b));
}
__device__ __forceinline__ float2 unpack2(ull v) {
    float2 f; asm("mov.b64 {%0, %1}, %2;" : "=f"(f.x), "=f"(f.y) : "l"(v)); return f;
}

// ---------------- device scratch (static: no allocations allowed) ----------
__device__ unsigned g_bar;                 // single grid-barrier counter
__device__ float g_h0T[HH*BB];             // transposed activations [h][b]
__device__ float g_h1T[HH*BB];
__device__ float g_rh0T[HH*BB];
__device__ float g_rh1T[HH*BB];
__device__ float g_gx0T[(long)MB*G3];      // [t][col][b]
__device__ float g_M1[HH*G3];              // fc0^T @ W_x1
__device__ float g_b1p[G3];
__device__ float g_Dmt[(long)VV*HH];       // dec_W @ fc1  (V x H)
__device__ float g_db2[VV];
__device__ float g_Hseq[(long)MB*HH];      // h1 per step, [t][b][h]

// ---------------- generic tiled GEMM 128x128x16 (FFMA2 inner) --------------
template<int OPA, int OPB, bool GATHER, bool BIAS, bool TOUT>
__global__ __launch_bounds__(256, 1)
void gemm128(const float* __restrict__ A, const float* __restrict__ B,
             const float* __restrict__ bias, const int* __restrict__ gidx,
             float* __restrict__ C, int M, int N, int K)
{
    const int BM = 128, BN = 128, BK = 16;
    __shared__ float As[BK][BM];
    __shared__ float Bs[BK][BN];
    const int m0 = blockIdx.y * BM;
    const int n0 = blockIdx.x * BN;
    const int tid = threadIdx.x;
    const int tm0 = (tid & 15) * 8;
    const int tn0 = (tid >> 4) * 8;
    ull acc[8][4];
#pragma unroll
    for (int i = 0; i < 8; i++)
#pragma unroll
        for (int j = 0; j < 4; j++) acc[i][j] = 0ULL;

    for (int k0 = 0; k0 < K; k0 += BK) {
        if (OPA == 0) {
            int kk = tid & 15, mr = tid >> 4;
#pragma unroll
            for (int i = 0; i < 8; i++) {
                int m = mr + i * 16;
                int gm = m0 + m;
                float v = 0.f;
                if (gm < M) {
                    long row = GATHER ? (long)gidx[gm] : (long)gm;
                    v = A[row * K + k0 + kk];
                }
                As[kk][m] = v;
            }
        } else {
            int m = tid & 127, kb = tid >> 7;
#pragma unroll
            for (int i = 0; i < 8; i++) {
                int kk = kb + i * 2;
                int gm = m0 + m;
                As[kk][m] = (gm < M) ? A[(long)(k0 + kk) * M + gm] : 0.f;
            }
        }
        if (OPB == 0) {
            int n = tid & 127, kb = tid >> 7;
#pragma unroll
            for (int i = 0; i < 8; i++) {
                int kk = kb + i * 2;
                int gn = n0 + n;
                Bs[kk][n] = (gn < N) ? B[(long)(k0 + kk) * N + gn] : 0.f;
            }
        } else {
            int kk = tid & 15, nr = tid >> 4;
#pragma unroll
            for (int i = 0; i < 8; i++) {
                int n = nr + i * 16;
                int gn = n0 + n;
                Bs[kk][n] = (gn < N) ? B[(long)gn * K + k0 + kk] : 0.f;
            }
        }
        __syncthreads();
#pragma unroll
        for (int kk = 0; kk < BK; kk++) {
            float a[8];
            *(float4*)&a[0] = *(const float4*)&As[kk][tm0];
            *(float4*)&a[4] = *(const float4*)&As[kk][tm0 + 4];
            ull b2[4];
            *(ulonglong2*)&b2[0] = *(const ulonglong2*)&Bs[kk][tn0];
            *(ulonglong2*)&b2[2] = *(const ulonglong2*)&Bs[kk][tn0 + 4];
#pragma unroll
            for (int i = 0; i < 8; i++) {
                ull ai = pack2(a[i], a[i]);
#pragma unroll
                for (int j = 0; j < 4; j++) ffma2(acc[i][j], ai, b2[j]);
            }
        }
        __syncthreads();
    }
#pragma unroll
    for (int i = 0; i < 8; i++) {
        int gm = m0 + tm0 + i;
        if (gm >= M) continue;
#pragma unroll
        for (int j2 = 0; j2 < 4; j2++) {
            float2 f = unpack2(acc[i][j2]);
#pragma unroll
            for (int u = 0; u < 2; u++) {
                int gn = n0 + tn0 + j2 * 2 + u;
                if (gn < N) {
                    float v = (u == 0) ? f.x : f.y;
                    if (BIAS) v += bias[gn];
                    long idx = TOUT ? (((long)(gm >> 6) * N + gn) * 64 + (gm & 63))
                                    : ((long)gm * N + gn);
                    C[idx] = v;
                }
            }
        }
    }
}

// ---------------- one-time small precomputes -------------------------------
__global__ void compute_b1p(const float* __restrict__ fcb0,
                            const float* __restrict__ Wx1,
                            const float* __restrict__ brzh1,
                            float* __restrict__ out)
{
    int j = blockIdx.x * 256 + threadIdx.x;
    if (j >= G3) return;
    float s = brzh1[j];
#pragma unroll 16
    for (int m = 0; m < HH; m++) s += __ldg(&fcb0[m]) * __ldg(&Wx1[m * G3 + j]);
    out[j] = s;
}

__global__ void compute_db2(const float* __restrict__ fcb1,
                            const float* __restrict__ decW,
                            const float* __restrict__ decb,
                            float* __restrict__ out)
{
    int v = (blockIdx.x * 256 + threadIdx.x) >> 5;
    int lane = threadIdx.x & 31;
    if (v >= VV) return;
    float s = 0.f;
    for (int j = lane; j < HH; j += 32) s += fcb1[j] * decW[v * HH + j];
#pragma unroll
    for (int o = 16; o; o >>= 1) s += __shfl_xor_sync(0xffffffffu, s, o);
    if (lane == 0) out[v] = s + decb[v];
}

__global__ void init_h(const float* __restrict__ hidden)
{
    int i = blockIdx.x * 256 + threadIdx.x;
    if (i == 0) g_bar = 0u;
    if (i < BB * HH) {
        int b = i >> 9, h = i & 511;
        g_h0T[h * 64 + b] = hidden[i];
        g_h1T[h * 64 + b] = hidden[BB * HH + i];
    }
}

__global__ void write_hfinal(float* __restrict__ out)
{
    int i = blockIdx.x * 256 + threadIdx.x;
    if (i < BB * HH) {
        int b = i >> 9, h = i & 511;
        out[i] = g_h0T[h * 64 + b];
        out[BB * HH + i] = g_h1T[h * 64 + b];
    }
}

// ---------------- cheap grid barrier ---------------------------------------
// release: one acq_rel fence + relaxed RED; wait: relaxed polls of ONE counter
// (no serialized acquire chain), then one acq_rel fence for acquire ordering.
__device__ __forceinline__ void gridbar(unsigned target)
{
    __syncthreads();
    if (threadIdx.x == 0) {
        asm volatile("fence.acq_rel.gpu;" ::: "memory");
        asm volatile("red.relaxed.gpu.global.add.u32 [%0], 1;" :: "l"(&g_bar) : "memory");
        unsigned v;
        do {
            asm volatile("ld.relaxed.gpu.global.u32 %0, [%1];"
                         : "=r"(v) : "l"(&g_bar) : "memory");
        } while (v < target);
        asm volatile("fence.acq_rel.gpu;" ::: "memory");
    }
    __syncthreads();
}

// smem layout (floats):
//   w[9*512*4]=18432 | bufs[2*8192]=16384 | ps[7*8*256]=14336 |
//   z0s[256] | z1s[256] | whxs[256]
#define SM_W   0
#define SM_BUF 18432
#define SM_PS  34816
#define SM_Z0  49152
#define SM_Z1  49408
#define SM_WX  49664
#define SM_FLOATS 49920   // 199680 bytes

// ---------------- persistent recurrent kernel (2 barriers / step) ----------
__global__ __launch_bounds__(512, 1)
void gru_persistent(const float* __restrict__ Uh0, const float* __restrict__ Uht0,
                    const float* __restrict__ Uh1, const float* __restrict__ Uht1)
{
    extern __shared__ float sm[];
    float* w    = sm + SM_W;   // groups: 0=Uh0r 1=Uh0z 2=Uht0 3=M1r 4=M1z 5=M1w 6=Uh1r 7=Uh1z 8=Uht1
    float* bufs = sm + SM_BUF;
    float* ps   = sm + SM_PS;
    float* z0s  = sm + SM_Z0;
    float* z1s  = sm + SM_Z1;
    float* whxs = sm + SM_WX;

    const int tid   = threadIdx.x;
    const int hbase = blockIdx.x * CH;

    // ---- stage weights into smem once: w[g*2048 + k*4 + c] ----
    for (int i = tid; i < 9 * 512 * 4; i += 512) {
        int c = i & 3, k = (i >> 2) & 511, g = i >> 11;
        float v;
        switch (g) {
            case 0:  v = Uh0[k * G2 + hbase + c]; break;
            case 1:  v = Uh0[k * G2 + 512 + hbase + c]; break;
            case 2:  v = Uht0[k * HH + hbase + c]; break;
            case 3:  v = g_M1[k * G3 + hbase + c]; break;
            case 4:  v = g_M1[k * G3 + 512 + hbase + c]; break;
            case 5:  v = g_M1[k * G3 + 1024 + hbase + c]; break;
            case 6:  v = Uh1[k * G2 + hbase + c]; break;
            case 7:  v = Uh1[k * G2 + 512 + hbase + c]; break;
            default: v = Uht1[k * HH + hbase + c]; break;
        }
        w[i] = v;
    }
    __syncthreads();

    const int b   = tid & 63;           // batch lane (compute role)
    const int ks  = tid >> 6;           // 0..7 k-slice (compute role)
    const int rb  = tid & 63;           // reducer batch
    const int rcl = (tid >> 6) & 3;     // reducer col (both halves)
    unsigned bcnt = 0;

    // Pipelined schedule: t=-1 is the prologue (A(0)/B(0) only).
    for (int t = -1; t < TT; t++) {
        const int tp1 = (t + 1 < TT) ? t + 1 : TT - 1;
        const bool doC = (t >= 0);

        // ========= Stage X: C(t) || A(t+1) =========
        {
            float gxr_pre = 0.f, gxz_pre = 0.f;
            if (tid >= 256) {
                gxr_pre = __ldg(&g_gx0T[((long)tp1 * G3 +       hbase + rcl) * 64 + rb]);
                gxz_pre = __ldg(&g_gx0T[((long)tp1 * G3 + 512 + hbase + rcl) * 64 + rb]);
            }
            ull a3x=0,a3y=0,a4x=0,a4y=0,a5x=0,a5y=0;   // M1 r,z,w (h0 phases)
            ull a0x=0,a0y=0,a1x=0,a1y=0;               // Uh0 r,z (h0 phases, for A')
            ull a6x=0,a6y=0,a7x=0,a7y=0;               // Uh1 r,z (h1 phases)
            const float4* s0 = (const float4*)g_h0T;
            const float4* s1 = (const float4*)g_h1T;
            float4 p0 = __ldcg(s0 + tid),        p1 = __ldcg(s0 + 512 + tid),
                   p2 = __ldcg(s0 + 1024 + tid), p3 = __ldcg(s0 + 1536 + tid);
#pragma unroll
            for (int ph = 0; ph < 8; ph++) {
                float* bp = bufs + (ph & 1) * 8192;
                ((float4*)bp)[tid] = p0; ((float4*)bp)[512 + tid] = p1;
                ((float4*)bp)[1024 + tid] = p2; ((float4*)bp)[1536 + tid] = p3;
                __syncthreads();
                if (ph < 7) {
                    const float4* sn = (ph + 1 < 4) ? s0 : s1;
                    const float4* sc = sn + ((ph + 1) & 3) * 2048;
                    p0 = __ldcg(sc + tid); p1 = __ldcg(sc + 512 + tid);
                    p2 = __ldcg(sc + 1024 + tid); p3 = __ldcg(sc + 1536 + tid);
                }
                const float* ap = bp + (ks * 16) * 64 + b;
                const int kk = ((ph & 3) * 128 + ks * 16) * 4;
                if (ph < 4) {
                    const float* w3 = w + 3 * 2048 + kk;
                    const float* w4 = w + 4 * 2048 + kk;
                    const float* w5 = w + 5 * 2048 + kk;
                    const float* w0 = w + 0 * 2048 + kk;
                    const float* w1 = w + 1 * 2048 + kk;
#pragma unroll
                    for (int j = 0; j < 16; j++) {
                        float a = ap[j * 64]; ull a2 = pack2(a, a);
                        ulonglong2 v3 = *(const ulonglong2*)(w3 + j * 4);
                        ulonglong2 v4 = *(const ulonglong2*)(w4 + j * 4);
                        ulonglong2 v5 = *(const ulonglong2*)(w5 + j * 4);
                        ulonglong2 v0 = *(const ulonglong2*)(w0 + j * 4);
                        ulonglong2 v1 = *(const ulonglong2*)(w1 + j * 4);
                        ffma2(a3x, a2, v3.x); ffma2(a3y, a2, v3.y);
                        ffma2(a4x, a2, v4.x); ffma2(a4y, a2, v4.y);
                        ffma2(a5x, a2, v5.x); ffma2(a5y, a2, v5.y);
                        ffma2(a0x, a2, v0.x); ffma2(a0y, a2, v0.y);
                        ffma2(a1x, a2, v1.x); ffma2(a1y, a2, v1.y);
                    }
                } else {
                    const float* w6 = w + 6 * 2048 + kk;
                    const float* w7 = w + 7 * 2048 + kk;
#pragma unroll
                    for (int j = 0; j < 16; j++) {
                        float a = ap[j * 64]; ull a2 = pack2(a, a);
                        ulonglong2 v6 = *(const ulonglong2*)(w6 + j * 4);
                        ulonglong2 v7 = *(const ulonglong2*)(w7 + j * 4);
                        ffma2(a6x, a2, v6.x); ffma2(a6y, a2, v6.y);
                        ffma2(a7x, a2, v7.x); ffma2(a7y, a2, v7.y);
                    }
                }
            }
            {   // psum groups g=0..6: m1r,m1z,m1w,u1r,u1z,Ar,Az
                float2 f; float* pp;
                pp = ps + (ks * 7 + 0) * 256 + b;
                f = unpack2(a3x); pp[0] = f.x; pp[64] = f.y;
                f = unpack2(a3y); pp[128] = f.x; pp[192] = f.y;
                pp = ps + (ks * 7 + 1) * 256 + b;
                f = unpack2(a4x); pp[0] = f.x; pp[64] = f.y;
                f = unpack2(a4y); pp[128] = f.x; pp[192] = f.y;
                pp = ps + (ks * 7 + 2) * 256 + b;
                f = unpack2(a5x); pp[0] = f.x; pp[64] = f.y;
                f = unpack2(a5y); pp[128] = f.x; pp[192] = f.y;
                pp = ps + (ks * 7 + 3) * 256 + b;
                f = unpack2(a6x); pp[0] = f.x; pp[64] = f.y;
                f = unpack2(a6y); pp[128] = f.x; pp[192] = f.y;
                pp = ps + (ks * 7 + 4) * 256 + b;
                f = unpack2(a7x); pp[0] = f.x; pp[64] = f.y;
                f = unpack2(a7y); pp[128] = f.x; pp[192] = f.y;
                pp = ps + (ks * 7 + 5) * 256 + b;
                f = unpack2(a0x); pp[0] = f.x; pp[64] = f.y;
                f = unpack2(a0y); pp[128] = f.x; pp[192] = f.y;
                pp = ps + (ks * 7 + 6) * 256 + b;
                f = unpack2(a1x); pp[0] = f.x; pp[64] = f.y;
                f = unpack2(a1y); pp[128] = f.x; pp[192] = f.y;
            }
            __syncthreads();
            if (tid < 256) {
                if (doC) {   // C(t) epilogue
                    float sr = 0.f, sz = 0.f, sw = 0.f;
#pragma unroll
                    for (int k2 = 0; k2 < 8; k2++) {
                        int base = k2 * 7 * 256 + rcl * 64 + rb;
                        sr += ps[base]           + ps[base + 3 * 256];
                        sz += ps[base + 256]     + ps[base + 4 * 256];
                        sw += ps[base + 2 * 256];
                    }
                    int col = hbase + rcl;
                    float r1v = 1.f / (1.f + expf(-(sr + __ldg(&g_b1p[col]))));
                    float z1v = 1.f / (1.f + expf(-(sz + __ldg(&g_b1p[512 + col]))));
                    float wx  = sw + __ldg(&g_b1p[1024 + col]);
                    float h1v = __ldcg(&g_h1T[col * 64 + rb]);
                    g_rh1T[col * 64 + rb] = r1v * h1v;
                    z1s[tid]  = z1v;
                    whxs[tid] = wx;
                }
            } else {         // A(t+1) epilogue
                float ar = 0.f, az = 0.f;
#pragma unroll
                for (int k2 = 0; k2 < 8; k2++) {
                    int base = k2 * 7 * 256 + rcl * 64 + rb;
                    ar += ps[base + 5 * 256];
                    az += ps[base + 6 * 256];
                }
                int col = hbase + rcl;
                float r0v = 1.f / (1.f + expf(-(ar + gxr_pre)));
                float z0v = 1.f / (1.f + expf(-(az + gxz_pre)));
                g_rh0T[col * 64 + rb] = r0v * __ldcg(&g_h0T[col * 64 + rb]);
                z0s[tid - 256] = z0v;
            }
        }
        bcnt += NBLK; gridbar(bcnt);

        // ========= Stage Y: D(t) || B(t+1) =========
        {
            float gxw_pre = 0.f;
            if (tid >= 256)
                gxw_pre = __ldg(&g_gx0T[((long)tp1 * G3 + 1024 + hbase + rcl) * 64 + rb]);
            ull d0 = 0, d1 = 0, e0 = 0, e1 = 0;
            const float4* sD = (const float4*)g_rh1T;
            const float4* sB = (const float4*)g_rh0T;
            float4 p0 = __ldcg(sD + tid),        p1 = __ldcg(sD + 512 + tid),
                   p2 = __ldcg(sD + 1024 + tid), p3 = __ldcg(sD + 1536 + tid);
#pragma unroll
            for (int ph = 0; ph < 8; ph++) {
                float* bp = bufs + (ph & 1) * 8192;
                ((float4*)bp)[tid] = p0; ((float4*)bp)[512 + tid] = p1;
                ((float4*)bp)[1024 + tid] = p2; ((float4*)bp)[1536 + tid] = p3;
                __syncthreads();
                if (ph < 7) {
                    const float4* sn = (ph + 1 < 4) ? sD : sB;
                    const float4* sc = sn + ((ph + 1) & 3) * 2048;
                    p0 = __ldcg(sc + tid); p1 = __ldcg(sc + 512 + tid);
                    p2 = __ldcg(sc + 1024 + tid); p3 = __ldcg(sc + 1536 + tid);
                }
                const float* ap = bp + (ks * 16) * 64 + b;
                const int kk = ((ph & 3) * 128 + ks * 16) * 4;
                if (ph < 4) {
                    const float* w8 = w + 8 * 2048 + kk;
#pragma unroll
                    for (int j = 0; j < 16; j++) {
                        float a = ap[j * 64]; ull a2 = pack2(a, a);
                        ulonglong2 v8 = *(const ulonglong2*)(w8 + j * 4);
                        ffma2(d0, a2, v8.x); ffma2(d1, a2, v8.y);
                    }
                } else {
                    const float* w2 = w + 2 * 2048 + kk;
#pragma unroll
                    for (int j = 0; j < 16; j++) {
                        float a = ap[j * 64]; ull a2 = pack2(a, a);
                        ulonglong2 v2 = *(const ulonglong2*)(w2 + j * 4);
                        ffma2(e0, a2, v2.x); ffma2(e1, a2, v2.y);
                    }
                }
            }
            {   // psum groups: 0 = D (Uht1), 1 = B' (Uht0)
                float2 f; float* pp;
                pp = ps + (ks * 2 + 0) * 256 + b;
                f = unpack2(d0); pp[0] = f.x; pp[64] = f.y;
                f = unpack2(d1); pp[128] = f.x; pp[192] = f.y;
                pp = ps + (ks * 2 + 1) * 256 + b;
                f = unpack2(e0); pp[0] = f.x; pp[64] = f.y;
                f = unpack2(e1); pp[128] = f.x; pp[192] = f.y;
            }
            __syncthreads();
            if (tid < 256) {
                if (doC) {   // D(t): update h1, emit Hseq
                    float sd = 0.f;
#pragma unroll
                    for (int k2 = 0; k2 < 8; k2++)
                        sd += ps[(k2 * 2 + 0) * 256 + rcl * 64 + rb];
                    int col = hbase + rcl;
                    float ht = tanhf(whxs[tid] + sd);
                    float z  = z1s[tid];
                    float hp = __ldcg(&g_h1T[col * 64 + rb]);
                    float hn = hp + z * (ht - hp);
                    g_h1T[col * 64 + rb] = hn;
                    g_Hseq[((long)t * 64 + rb) * 512 + col] = hn;
                }
            } else {
                if (t + 1 < TT) {   // B(t+1): update h0 (write-guarded at end)
                    float sb = 0.f;
#pragma unroll
                    for (int k2 = 0; k2 < 8; k2++)
                        sb += ps[(k2 * 2 + 1) * 256 + rcl * 64 + rb];
                    int col = hbase + rcl;
                    float ht = tanhf(gxw_pre + sb);
                    float z  = z0s[tid - 256];
                    float hp = __ldcg(&g_h0T[col * 64 + rb]);
                    g_h0T[col * 64 + rb] = hp + z * (ht - hp);
                }
            }
        }
        bcnt += NBLK; gridbar(bcnt);
    }
}

// ---------------- host launch ----------------------------------------------
extern "C" void kernel_launch(void* const* d_in, const int* in_sizes, int n_in,
                              void* d_out, int out_size)
{
    const int*   inputs = (const int*)  d_in[0];            // (T,B)
    const float* hidden = (const float*)d_in[1];            // (2,B,H)
    const float* embt   = (const float*)d_in[2];            // (V,E)
    const float* W_x    = (const float*)d_in[3];            // (2,H,3H)
    const float* U_h    = (const float*)d_in[4];            // (2,H,2H)
    const float* U_ht   = (const float*)d_in[5];            // (2,H,H)
    const float* b_rzh  = (const float*)d_in[6];            // (2,3H)
    const float* fc_W   = (const float*)d_in[7];            // (2,H,H)
    const float* fc_b   = (const float*)d_in[8];            // (2,H)
    const float* dec_W  = (const float*)d_in[9];            // (V,H)
    const float* dec_b  = (const float*)d_in[10];           // (V,)
    float* out = (float*)d_out;

    const float* W_x0  = W_x;
    const float* W_x1  = W_x + HH * G3;
    const float* U_h0  = U_h;
    const float* U_h1  = U_h + HH * G2;
    const float* U_ht0 = U_ht;
    const float* U_ht1 = U_ht + HH * HH;
    const float* fc0   = fc_W;
    const float* fc1   = fc_W + HH * HH;

    float* pGX0 = nullptr; cudaGetSymbolAddress((void**)&pGX0, g_gx0T);
    float* pM1  = nullptr; cudaGetSymbolAddress((void**)&pM1,  g_M1);
    float* pB1p = nullptr; cudaGetSymbolAddress((void**)&pB1p, g_b1p);
    float* pDmt = nullptr; cudaGetSymbolAddress((void**)&pDmt, g_Dmt);
    float* pDb2 = nullptr; cudaGetSymbolAddress((void**)&pDb2, g_db2);
    float* pHsq = nullptr; cudaGetSymbolAddress((void**)&pHsq, g_Hseq);

    static bool attr_set = false;
    if (!attr_set) {
        cudaFuncSetAttribute(gru_persistent,
                             cudaFuncAttributeMaxDynamicSharedMemorySize,
                             SM_FLOATS * sizeof(float));
        attr_set = true;
    }

    // 0) init h (transposed) + barrier counter
    init_h<<<(BB * HH + 255) / 256, 256>>>(hidden);

    // 1) GX0^T = (gather(emb) @ W_x0 + b_rzh0) -> [t][col][b]
    gemm128<0, 0, true, true, true><<<dim3(G3 / 128, MB / 128), 256>>>(
        embt, W_x0, b_rzh, inputs, pGX0, MB, G3, HH);

    // 2) M1 = fc0^T @ W_x1, b1' = fc_b0 @ W_x1 + b_rzh1
    gemm128<1, 0, false, false, false><<<dim3(G3 / 128, HH / 128), 256>>>(
        fc0, W_x1, nullptr, nullptr, pM1, HH, G3, HH);
    compute_b1p<<<(G3 + 255) / 256, 256>>>(fc_b, W_x1, b_rzh + G3, pB1p);

    // 3) Dmt = dec_W @ fc1  (V x H), db2 = dec_W @ fc_b1 + dec_b
    gemm128<0, 0, false, false, false><<<dim3(HH / 128, (VV + 127) / 128), 256>>>(
        dec_W, fc1, nullptr, nullptr, pDmt, VV, HH, HH);
    compute_db2<<<(VV * 32 + 255) / 256, 256>>>(fc_b + HH, dec_W, dec_b, pDb2);

    // 4) entire 128-step recurrence in ONE persistent kernel (2 syncs/step)
    gru_persistent<<<NBLK, 512, SM_FLOATS * sizeof(float)>>>(
        U_h0, U_ht0, U_h1, U_ht1);

    // 5) logits = Hseq[8192 x 512] @ Dmt^T + db2
    gemm128<0, 1, false, true, false><<<dim3((VV + 127) / 128, MB / 128), 256>>>(
        pHsq, pDmt, pDb2, nullptr, out, MB, VV, HH);

    // 6) h_final appended after logits (if harness expects it)
    if (out_size >= (long)MB * VV + 2 * BB * HH) {
        write_hfinal<<<(BB * HH + 255) / 256, 256>>>(out + (long)MB * VV);
    }
}

// round 15
// speedup vs baseline: 6.1137x; 1.4653x over previous
#include <cuda_runtime.h>
#include <cuda_bf16.h>
#include <math.h>
#include <stdint.h>

// Problem constants
#define TT   128
#define BB   64
#define HH   512
#define VV   10000
#define G3   1536   // 3*H
#define G2   1024   // 2*H
#define MB   (TT*BB)   // 8192 rows
#define NBLK 128       // persistent blocks
#define CH   4         // h-columns owned per block
#define VPAD 10240     // VV padded to 128 multiple

typedef unsigned long long ull;

// ---------------- f32x2 packed-FMA helpers (Blackwell FFMA2) ---------------
__device__ __forceinline__ ull pack2(float x, float y) {
    ull r; asm("mov.b64 %0, {%1, %2};" : "=l"(r) : "f"(x), "f"(y)); return r;
}
__device__ __forceinline__ void ffma2(ull& d, ull a, ull b) {
    asm("fma.rn.f32x2 %0, %1, %2, %0;" : "+l"(d) : "l"(a), "l"(b));
}
__device__ __forceinline__ float2 unpack2(ull v) {
    float2 f; asm("mov.b64 {%0, %1}, %2;" : "=f"(f.x), "=f"(f.y) : "l"(v)); return f;
}

#define SWZ128(o) ((o) ^ (((o) >> 3) & 0x70))

__device__ __forceinline__ unsigned smem_u32(const void* p) {
    unsigned a;
    asm("{ .reg .u64 t; cvta.to.shared.u64 t, %1; cvt.u32.u64 %0, t; }"
        : "=r"(a) : "l"(p));
    return a;
}

// ---------------- device scratch (static: no allocations allowed) ----------
__device__ unsigned g_bar;                 // single grid-barrier counter
__device__ float g_h0T[HH*BB];             // transposed activations [h][b]
__device__ float g_h1T[HH*BB];
__device__ float g_rh0T[HH*BB];
__device__ float g_rh1T[HH*BB];
__device__ float g_gx0T[(long)MB*G3];      // [t][col][b]
__device__ float g_M1[HH*G3];              // fc0^T @ W_x1
__device__ float g_b1p[G3];
__device__ float g_Dmt[(long)VV*HH];       // dec_W @ fc1  (V x H)
__device__ float g_db2[VV];
__device__ float g_Hseq[(long)MB*HH];      // h1 per step, [t][b][h]
__device__ __nv_bfloat16 g_A2[(long)MB*G3];    // [Hh | Hh | Hl]  8192 x 1536
__device__ __nv_bfloat16 g_B2[(long)VPAD*G3];  // [Dh | Dl | Dh]  10240 x 1536

// ---------------- generic tiled GEMM 128x128x16 (FFMA2 inner) --------------
template<int OPA, int OPB, bool GATHER, bool BIAS, bool TOUT>
__global__ __launch_bounds__(256, 1)
void gemm128(const float* __restrict__ A, const float* __restrict__ B,
             const float* __restrict__ bias, const int* __restrict__ gidx,
             float* __restrict__ C, int M, int N, int K)
{
    const int BM = 128, BN = 128, BK = 16;
    __shared__ float As[BK][BM];
    __shared__ float Bs[BK][BN];
    const int m0 = blockIdx.y * BM;
    const int n0 = blockIdx.x * BN;
    const int tid = threadIdx.x;
    const int tm0 = (tid & 15) * 8;
    const int tn0 = (tid >> 4) * 8;
    ull acc[8][4];
#pragma unroll
    for (int i = 0; i < 8; i++)
#pragma unroll
        for (int j = 0; j < 4; j++) acc[i][j] = 0ULL;

    for (int k0 = 0; k0 < K; k0 += BK) {
        if (OPA == 0) {
            int kk = tid & 15, mr = tid >> 4;
#pragma unroll
            for (int i = 0; i < 8; i++) {
                int m = mr + i * 16;
                int gm = m0 + m;
                float v = 0.f;
                if (gm < M) {
                    long row = GATHER ? (long)gidx[gm] : (long)gm;
                    v = A[row * K + k0 + kk];
                }
                As[kk][m] = v;
            }
        } else {
            int m = tid & 127, kb = tid >> 7;
#pragma unroll
            for (int i = 0; i < 8; i++) {
                int kk = kb + i * 2;
                int gm = m0 + m;
                As[kk][m] = (gm < M) ? A[(long)(k0 + kk) * M + gm] : 0.f;
            }
        }
        if (OPB == 0) {
            int n = tid & 127, kb = tid >> 7;
#pragma unroll
            for (int i = 0; i < 8; i++) {
                int kk = kb + i * 2;
                int gn = n0 + n;
                Bs[kk][n] = (gn < N) ? B[(long)(k0 + kk) * N + gn] : 0.f;
            }
        } else {
            int kk = tid & 15, nr = tid >> 4;
#pragma unroll
            for (int i = 0; i < 8; i++) {
                int n = nr + i * 16;
                int gn = n0 + n;
                Bs[kk][n] = (gn < N) ? B[(long)gn * K + k0 + kk] : 0.f;
            }
        }
        __syncthreads();
#pragma unroll
        for (int kk = 0; kk < BK; kk++) {
            float a[8];
            *(float4*)&a[0] = *(const float4*)&As[kk][tm0];
            *(float4*)&a[4] = *(const float4*)&As[kk][tm0 + 4];
            ull b2[4];
            *(ulonglong2*)&b2[0] = *(const ulonglong2*)&Bs[kk][tn0];
            *(ulonglong2*)&b2[2] = *(const ulonglong2*)&Bs[kk][tn0 + 4];
#pragma unroll
            for (int i = 0; i < 8; i++) {
                ull ai = pack2(a[i], a[i]);
#pragma unroll
                for (int j = 0; j < 4; j++) ffma2(acc[i][j], ai, b2[j]);
            }
        }
        __syncthreads();
    }
#pragma unroll
    for (int i = 0; i < 8; i++) {
        int gm = m0 + tm0 + i;
        if (gm >= M) continue;
#pragma unroll
        for (int j2 = 0; j2 < 4; j2++) {
            float2 f = unpack2(acc[i][j2]);
#pragma unroll
            for (int u = 0; u < 2; u++) {
                int gn = n0 + tn0 + j2 * 2 + u;
                if (gn < N) {
                    float v = (u == 0) ? f.x : f.y;
                    if (BIAS) v += bias[gn];
                    long idx = TOUT ? (((long)(gm >> 6) * N + gn) * 64 + (gm & 63))
                                    : ((long)gm * N + gn);
                    C[idx] = v;
                }
            }
        }
    }
}

// ---------------- one-time small precomputes -------------------------------
__global__ void compute_b1p(const float* __restrict__ fcb0,
                            const float* __restrict__ Wx1,
                            const float* __restrict__ brzh1,
                            float* __restrict__ out)
{
    int wj = (blockIdx.x * 256 + threadIdx.x) >> 5;
    int lane = threadIdx.x & 31;
    if (wj >= G3) return;
    float s = 0.f;
    for (int m = lane; m < HH; m += 32)
        s += __ldg(&fcb0[m]) * __ldg(&Wx1[m * G3 + wj]);
#pragma unroll
    for (int o = 16; o; o >>= 1) s += __shfl_xor_sync(0xffffffffu, s, o);
    if (lane == 0) out[wj] = s + brzh1[wj];
}

__global__ void compute_db2(const float* __restrict__ fcb1,
                            const float* __restrict__ decW,
                            const float* __restrict__ decb,
                            float* __restrict__ out)
{
    int v = (blockIdx.x * 256 + threadIdx.x) >> 5;
    int lane = threadIdx.x & 31;
    if (v >= VV) return;
    float s = 0.f;
    for (int j = lane; j < HH; j += 32) s += fcb1[j] * decW[v * HH + j];
#pragma unroll
    for (int o = 16; o; o >>= 1) s += __shfl_xor_sync(0xffffffffu, s, o);
    if (lane == 0) out[v] = s + decb[v];
}

// bf16 hi/lo split of decoder weights: B2 = [Dh | Dl | Dh] (rows padded)
__global__ void split_D()
{
    long i = (long)blockIdx.x * 256 + threadIdx.x;
    if (i >= (long)VPAD * HH) return;
    long v = i >> 9; int k = (int)(i & 511);
    __nv_bfloat16 hi, lo;
    if (v < VV) {
        float x = g_Dmt[v * HH + k];
        hi = __float2bfloat16(x);
        lo = __float2bfloat16(x - __bfloat162float(hi));
    } else {
        hi = __float2bfloat16(0.f); lo = hi;
    }
    long base = v * G3 + k;
    g_B2[base]        = hi;
    g_B2[base + 512]  = lo;
    g_B2[base + 1024] = hi;
}

// bf16 hi/lo split of Hseq: A2 = [Hh | Hh | Hl]
__global__ void split_H()
{
    long i = (long)blockIdx.x * 256 + threadIdx.x;
    if (i >= (long)MB * HH) return;
    long m = i >> 9; int k = (int)(i & 511);
    float x = g_Hseq[m * HH + k];
    __nv_bfloat16 hi = __float2bfloat16(x);
    __nv_bfloat16 lo = __float2bfloat16(x - __bfloat162float(hi));
    long base = m * G3 + k;
    g_A2[base]        = hi;
    g_A2[base + 512]  = hi;
    g_A2[base + 1024] = lo;
}

__global__ void init_h(const float* __restrict__ hidden)
{
    int i = blockIdx.x * 256 + threadIdx.x;
    if (i == 0) g_bar = 0u;
    if (i < BB * HH) {
        int b = i >> 9, h = i & 511;
        g_h0T[h * 64 + b] = hidden[i];
        g_h1T[h * 64 + b] = hidden[BB * HH + i];
    }
}

__global__ void write_hfinal(float* __restrict__ out)
{
    int i = blockIdx.x * 256 + threadIdx.x;
    if (i < BB * HH) {
        int b = i >> 9, h = i & 511;
        out[i] = g_h0T[h * 64 + b];
        out[BB * HH + i] = g_h1T[h * 64 + b];
    }
}

// ---------------- mma.sync bf16 decoder GEMM -------------------------------
// out[8192 x 10000] = A2[8192 x 1536]bf16 @ B2[10240 x 1536]bf16^T + db2
// Tile 128(M) x 128(N); 8 warps, warp tile 64x32 (4x4 m16n8k16 frags).
// K chunks of 64 bf16 in SW128-swizzled smem; double-buffered, 1 sync/chunk.
#define DC_NCH  24          // 1536 / 64
#define DC_SMEM 66560       // 1024 align slack + 2*16K(A) + 2*16K(B)

__global__ __launch_bounds__(256, 2)
void mma_decoder(float* __restrict__ out)
{
    extern __shared__ char dsm_raw[];
    char* dsm = (char*)(((uintptr_t)dsm_raw + 1023) & ~(uintptr_t)1023);
    char* bufA[2] = { dsm,          dsm + 16384 };
    char* bufB[2] = { dsm + 32768,  dsm + 49152 };

    const int tid  = threadIdx.x;
    const int wid  = tid >> 5;
    const int lane = tid & 31;
    const long m0  = (long)blockIdx.y * 128;
    const long n0t = (long)blockIdx.x * 128;
    const int wm = wid & 1;        // 0..1  -> rows wm*64
    const int wn = wid >> 1;       // 0..3  -> cols wn*32

    float acc[4][4][4];
#pragma unroll
    for (int i = 0; i < 4; i++)
#pragma unroll
        for (int j = 0; j < 4; j++)
#pragma unroll
            for (int q = 0; q < 4; q++) acc[i][j][q] = 0.f;

    // per-thread load indices (A: 4 x uint4, B: 4 x uint4 per chunk)
    const int lrow = tid >> 3, lseg = tid & 7;

#define LOAD_CHUNK(c) do {                                                    \
    int _kc = (c) * 64; int _bf = (c) & 1;                                    \
    _Pragma("unroll")                                                         \
    for (int _i = 0; _i < 4; _i++) {                                          \
        int _row = lrow + _i * 32;                                            \
        uint4 _v = __ldg((const uint4*)(g_A2 + (m0 + _row) * G3 + _kc) + lseg); \
        *(uint4*)(bufA[_bf] + SWZ128(_row * 128 + lseg * 16)) = _v;           \
        uint4 _w = __ldg((const uint4*)(g_B2 + (n0t + _row) * G3 + _kc) + lseg); \
        *(uint4*)(bufB[_bf] + SWZ128(_row * 128 + lseg * 16)) = _w;           \
    }                                                                         \
} while (0)

    LOAD_CHUNK(0);
    __syncthreads();

    for (int c = 0; c < DC_NCH; c++) {
        if (c + 1 < DC_NCH) LOAD_CHUNK(c + 1);
        const unsigned abase = smem_u32(bufA[c & 1]);
        const unsigned bbase = smem_u32(bufB[c & 1]);
#pragma unroll
        for (int kk = 0; kk < 64; kk += 16) {
            unsigned a[4][4];
#pragma unroll
            for (int mi = 0; mi < 4; mi++) {
                int row  = wm * 64 + mi * 16 + (lane & 15);
                int colB = kk * 2 + (lane >> 4) * 16;
                unsigned ad = abase + SWZ128(row * 128 + colB);
                asm volatile("ldmatrix.sync.aligned.m8n8.x4.shared.b16 "
                             "{%0,%1,%2,%3}, [%4];"
                             : "=r"(a[mi][0]), "=r"(a[mi][1]),
                               "=r"(a[mi][2]), "=r"(a[mi][3]) : "r"(ad));
            }
            unsigned b[4][2];
#pragma unroll
            for (int nb = 0; nb < 2; nb++) {
                int row  = wn * 32 + nb * 16 + ((lane >> 4) & 1) * 8 + (lane & 7);
                int colB = kk * 2 + ((lane >> 3) & 1) * 16;
                unsigned bd = bbase + SWZ128(row * 128 + colB);
                unsigned r0, r1, r2, r3;
                asm volatile("ldmatrix.sync.aligned.m8n8.x4.shared.b16 "
                             "{%0,%1,%2,%3}, [%4];"
                             : "=r"(r0), "=r"(r1), "=r"(r2), "=r"(r3) : "r"(bd));
                b[nb * 2][0] = r0;     b[nb * 2][1] = r1;
                b[nb * 2 + 1][0] = r2; b[nb * 2 + 1][1] = r3;
            }
#pragma unroll
            for (int mi = 0; mi < 4; mi++)
#pragma unroll
                for (int ni = 0; ni < 4; ni++)
                    asm volatile(
                        "mma.sync.aligned.m16n8k16.row.col.f32.bf16.bf16.f32 "
                        "{%0,%1,%2,%3}, {%4,%5,%6,%7}, {%8,%9}, {%0,%1,%2,%3};"
                        : "+f"(acc[mi][ni][0]), "+f"(acc[mi][ni][1]),
                          "+f"(acc[mi][ni][2]), "+f"(acc[mi][ni][3])
                        : "r"(a[mi][0]), "r"(a[mi][1]),
                          "r"(a[mi][2]), "r"(a[mi][3]),
                          "r"(b[ni][0]), "r"(b[ni][1]));
        }
        __syncthreads();
    }
#undef LOAD_CHUNK

    // epilogue: C frag layout: c0,c1 -> (row = lane>>2, col = (lane&3)*2, +1);
    //           c2,c3 -> (row+8, same cols)
#pragma unroll
    for (int mi = 0; mi < 4; mi++) {
        long r0 = m0 + wm * 64 + mi * 16 + (lane >> 2);
        float* op0 = out + r0 * VV;
        float* op1 = out + (r0 + 8) * VV;
#pragma unroll
        for (int ni = 0; ni < 4; ni++) {
            long n = n0t + wn * 32 + ni * 8 + (lane & 3) * 2;
            if (n + 1 < VV) {
                float d0 = __ldg(&g_db2[n]), d1 = __ldg(&g_db2[n + 1]);
                op0[n]     = acc[mi][ni][0] + d0;
                op0[n + 1] = acc[mi][ni][1] + d1;
                op1[n]     = acc[mi][ni][2] + d0;
                op1[n + 1] = acc[mi][ni][3] + d1;
            } else {
                if (n < VV) {
                    float d0 = __ldg(&g_db2[n]);
                    op0[n] = acc[mi][ni][0] + d0;
                    op1[n] = acc[mi][ni][2] + d0;
                }
            }
        }
    }
}

// ---------------- cheap grid barrier ---------------------------------------
__device__ __forceinline__ void gridbar(unsigned target)
{
    __syncthreads();
    if (threadIdx.x == 0) {
        asm volatile("fence.acq_rel.gpu;" ::: "memory");
        asm volatile("red.relaxed.gpu.global.add.u32 [%0], 1;" :: "l"(&g_bar) : "memory");
        unsigned v;
        do {
            asm volatile("ld.relaxed.gpu.global.u32 %0, [%1];"
                         : "=r"(v) : "l"(&g_bar) : "memory");
        } while (v < target);
        asm volatile("fence.acq_rel.gpu;" ::: "memory");
    }
    __syncthreads();
}

// smem layout (floats):
//   w[9*512*4]=18432 | bufs[2*8192]=16384 | ps[7*8*256]=14336 |
//   z0s[256] | z1s[256] | whxs[256]
#define SM_W   0
#define SM_BUF 18432
#define SM_PS  34816
#define SM_Z0  49152
#define SM_Z1  49408
#define SM_WX  49664
#define SM_FLOATS 49920   // 199680 bytes

// ---------------- persistent recurrent kernel (2 barriers / step) ----------
__global__ __launch_bounds__(512, 1)
void gru_persistent(const float* __restrict__ Uh0, const float* __restrict__ Uht0,
                    const float* __restrict__ Uh1, const float* __restrict__ Uht1)
{
    extern __shared__ float sm[];
    float* w    = sm + SM_W;   // groups: 0=Uh0r 1=Uh0z 2=Uht0 3=M1r 4=M1z 5=M1w 6=Uh1r 7=Uh1z 8=Uht1
    float* bufs = sm + SM_BUF;
    float* ps   = sm + SM_PS;
    float* z0s  = sm + SM_Z0;
    float* z1s  = sm + SM_Z1;
    float* whxs = sm + SM_WX;

    const int tid   = threadIdx.x;
    const int hbase = blockIdx.x * CH;

    for (int i = tid; i < 9 * 512 * 4; i += 512) {
        int c = i & 3, k = (i >> 2) & 511, g = i >> 11;
        float v;
        switch (g) {
            case 0:  v = Uh0[k * G2 + hbase + c]; break;
            case 1:  v = Uh0[k * G2 + 512 + hbase + c]; break;
            case 2:  v = Uht0[k * HH + hbase + c]; break;
            case 3:  v = g_M1[k * G3 + hbase + c]; break;
            case 4:  v = g_M1[k * G3 + 512 + hbase + c]; break;
            case 5:  v = g_M1[k * G3 + 1024 + hbase + c]; break;
            case 6:  v = Uh1[k * G2 + hbase + c]; break;
            case 7:  v = Uh1[k * G2 + 512 + hbase + c]; break;
            default: v = Uht1[k * HH + hbase + c]; break;
        }
        w[i] = v;
    }
    __syncthreads();

    const int b   = tid & 63;
    const int ks  = tid >> 6;
    const int rb  = tid & 63;
    const int rcl = (tid >> 6) & 3;
    unsigned bcnt = 0;

    for (int t = -1; t < TT; t++) {
        const int tp1 = (t + 1 < TT) ? t + 1 : TT - 1;
        const bool doC = (t >= 0);

        // ========= Stage X: C(t) || A(t+1) =========
        {
            float gxr_pre = 0.f, gxz_pre = 0.f;
            if (tid >= 256) {
                gxr_pre = __ldg(&g_gx0T[((long)tp1 * G3 +       hbase + rcl) * 64 + rb]);
                gxz_pre = __ldg(&g_gx0T[((long)tp1 * G3 + 512 + hbase + rcl) * 64 + rb]);
            }
            ull a3x=0,a3y=0,a4x=0,a4y=0,a5x=0,a5y=0;
            ull a0x=0,a0y=0,a1x=0,a1y=0;
            ull a6x=0,a6y=0,a7x=0,a7y=0;
            const float4* s0 = (const float4*)g_h0T;
            const float4* s1 = (const float4*)g_h1T;
            float4 p0 = __ldcg(s0 + tid),        p1 = __ldcg(s0 + 512 + tid),
                   p2 = __ldcg(s0 + 1024 + tid), p3 = __ldcg(s0 + 1536 + tid);
#pragma unroll
            for (int ph = 0; ph < 8; ph++) {
                float* bp = bufs + (ph & 1) * 8192;
                ((float4*)bp)[tid] = p0; ((float4*)bp)[512 + tid] = p1;
                ((float4*)bp)[1024 + tid] = p2; ((float4*)bp)[1536 + tid] = p3;
                __syncthreads();
                if (ph < 7) {
                    const float4* sn = (ph + 1 < 4) ? s0 : s1;
                    const float4* sc = sn + ((ph + 1) & 3) * 2048;
                    p0 = __ldcg(sc + tid); p1 = __ldcg(sc + 512 + tid);
                    p2 = __ldcg(sc + 1024 + tid); p3 = __ldcg(sc + 1536 + tid);
                }
                const float* ap = bp + (ks * 16) * 64 + b;
                const int kk = ((ph & 3) * 128 + ks * 16) * 4;
                if (ph < 4) {
                    const float* w3 = w + 3 * 2048 + kk;
                    const float* w4 = w + 4 * 2048 + kk;
                    const float* w5 = w + 5 * 2048 + kk;
                    const float* w0 = w + 0 * 2048 + kk;
                    const float* w1 = w + 1 * 2048 + kk;
#pragma unroll
                    for (int j = 0; j < 16; j++) {
                        float a = ap[j * 64]; ull a2 = pack2(a, a);
                        ulonglong2 v3 = *(const ulonglong2*)(w3 + j * 4);
                        ulonglong2 v4 = *(const ulonglong2*)(w4 + j * 4);
                        ulonglong2 v5 = *(const ulonglong2*)(w5 + j * 4);
                        ulonglong2 v0 = *(const ulonglong2*)(w0 + j * 4);
                        ulonglong2 v1 = *(const ulonglong2*)(w1 + j * 4);
                        ffma2(a3x, a2, v3.x); ffma2(a3y, a2, v3.y);
                        ffma2(a4x, a2, v4.x); ffma2(a4y, a2, v4.y);
                        ffma2(a5x, a2, v5.x); ffma2(a5y, a2, v5.y);
                        ffma2(a0x, a2, v0.x); ffma2(a0y, a2, v0.y);
                        ffma2(a1x, a2, v1.x); ffma2(a1y, a2, v1.y);
                    }
                } else {
                    const float* w6 = w + 6 * 2048 + kk;
                    const float* w7 = w + 7 * 2048 + kk;
#pragma unroll
                    for (int j = 0; j < 16; j++) {
                        float a = ap[j * 64]; ull a2 = pack2(a, a);
                        ulonglong2 v6 = *(const ulonglong2*)(w6 + j * 4);
                        ulonglong2 v7 = *(const ulonglong2*)(w7 + j * 4);
                        ffma2(a6x, a2, v6.x); ffma2(a6y, a2, v6.y);
                        ffma2(a7x, a2, v7.x); ffma2(a7y, a2, v7.y);
                    }
                }
            }
            {
                float2 f; float* pp;
                pp = ps + (ks * 7 + 0) * 256 + b;
                f = unpack2(a3x); pp[0] = f.x; pp[64] = f.y;
                f = unpack2(a3y); pp[128] = f.x; pp[192] = f.y;
                pp = ps + (ks * 7 + 1) * 256 + b;
                f = unpack2(a4x); pp[0] = f.x; pp[64] = f.y;
                f = unpack2(a4y); pp[128] = f.x; pp[192] = f.y;
                pp = ps + (ks * 7 + 2) * 256 + b;
                f = unpack2(a5x); pp[0] = f.x; pp[64] = f.y;
                f = unpack2(a5y); pp[128] = f.x; pp[192] = f.y;
                pp = ps + (ks * 7 + 3) * 256 + b;
                f = unpack2(a6x); pp[0] = f.x; pp[64] = f.y;
                f = unpack2(a6y); pp[128] = f.x; pp[192] = f.y;
                pp = ps + (ks * 7 + 4) * 256 + b;
                f = unpack2(a7x); pp[0] = f.x; pp[64] = f.y;
                f = unpack2(a7y); pp[128] = f.x; pp[192] = f.y;
                pp = ps + (ks * 7 + 5) * 256 + b;
                f = unpack2(a0x); pp[0] = f.x; pp[64] = f.y;
                f = unpack2(a0y); pp[128] = f.x; pp[192] = f.y;
                pp = ps + (ks * 7 + 6) * 256 + b;
                f = unpack2(a1x); pp[0] = f.x; pp[64] = f.y;
                f = unpack2(a1y); pp[128] = f.x; pp[192] = f.y;
            }
            __syncthreads();
            if (tid < 256) {
                if (doC) {
                    float sr = 0.f, sz = 0.f, sw = 0.f;
#pragma unroll
                    for (int k2 = 0; k2 < 8; k2++) {
                        int base = k2 * 7 * 256 + rcl * 64 + rb;
                        sr += ps[base]           + ps[base + 3 * 256];
                        sz += ps[base + 256]     + ps[base + 4 * 256];
                        sw += ps[base + 2 * 256];
                    }
                    int col = hbase + rcl;
                    float r1v = 1.f / (1.f + expf(-(sr + __ldg(&g_b1p[col]))));
                    float z1v = 1.f / (1.f + expf(-(sz + __ldg(&g_b1p[512 + col]))));
                    float wx  = sw + __ldg(&g_b1p[1024 + col]);
                    float h1v = __ldcg(&g_h1T[col * 64 + rb]);
                    g_rh1T[col * 64 + rb] = r1v * h1v;
                    z1s[tid]  = z1v;
                    whxs[tid] = wx;
                }
            } else {
                float ar = 0.f, az = 0.f;
#pragma unroll
                for (int k2 = 0; k2 < 8; k2++) {
                    int base = k2 * 7 * 256 + rcl * 64 + rb;
                    ar += ps[base + 5 * 256];
                    az += ps[base + 6 * 256];
                }
                int col = hbase + rcl;
                float r0v = 1.f / (1.f + expf(-(ar + gxr_pre)));
                float z0v = 1.f / (1.f + expf(-(az + gxz_pre)));
                g_rh0T[col * 64 + rb] = r0v * __ldcg(&g_h0T[col * 64 + rb]);
                z0s[tid - 256] = z0v;
            }
        }
        bcnt += NBLK; gridbar(bcnt);

        // ========= Stage Y: D(t) || B(t+1) =========
        {
            float gxw_pre = 0.f;
            if (tid >= 256)
                gxw_pre = __ldg(&g_gx0T[((long)tp1 * G3 + 1024 + hbase + rcl) * 64 + rb]);
            ull d0 = 0, d1 = 0, e0 = 0, e1 = 0;
            const float4* sD = (const float4*)g_rh1T;
            const float4* sB = (const float4*)g_rh0T;
            float4 p0 = __ldcg(sD + tid),        p1 = __ldcg(sD + 512 + tid),
                   p2 = __ldcg(sD + 1024 + tid), p3 = __ldcg(sD + 1536 + tid);
#pragma unroll
            for (int ph = 0; ph < 8; ph++) {
                float* bp = bufs + (ph & 1) * 8192;
                ((float4*)bp)[tid] = p0; ((float4*)bp)[512 + tid] = p1;
                ((float4*)bp)[1024 + tid] = p2; ((float4*)bp)[1536 + tid] = p3;
                __syncthreads();
                if (ph < 7) {
                    const float4* sn = (ph + 1 < 4) ? sD : sB;
                    const float4* sc = sn + ((ph + 1) & 3) * 2048;
                    p0 = __ldcg(sc + tid); p1 = __ldcg(sc + 512 + tid);
                    p2 = __ldcg(sc + 1024 + tid); p3 = __ldcg(sc + 1536 + tid);
                }
                const float* ap = bp + (ks * 16) * 64 + b;
                const int kk = ((ph & 3) * 128 + ks * 16) * 4;
                if (ph < 4) {
                    const float* w8 = w + 8 * 2048 + kk;
#pragma unroll
                    for (int j = 0; j < 16; j++) {
                        float a = ap[j * 64]; ull a2 = pack2(a, a);
                        ulonglong2 v8 = *(const ulonglong2*)(w8 + j * 4);
                        ffma2(d0, a2, v8.x); ffma2(d1, a2, v8.y);
                    }
                } else {
                    const float* w2 = w + 2 * 2048 + kk;
#pragma unroll
                    for (int j = 0; j < 16; j++) {
                        float a = ap[j * 64]; ull a2 = pack2(a, a);
                        ulonglong2 v2 = *(const ulonglong2*)(w2 + j * 4);
                        ffma2(e0, a2, v2.x); ffma2(e1, a2, v2.y);
                    }
                }
            }
            {
                float2 f; float* pp;
                pp = ps + (ks * 2 + 0) * 256 + b;
                f = unpack2(d0); pp[0] = f.x; pp[64] = f.y;
                f = unpack2(d1); pp[128] = f.x; pp[192] = f.y;
                pp = ps + (ks * 2 + 1) * 256 + b;
                f = unpack2(e0); pp[0] = f.x; pp[64] = f.y;
                f = unpack2(e1); pp[128] = f.x; pp[192] = f.y;
            }
            __syncthreads();
            if (tid < 256) {
                if (doC) {
                    float sd = 0.f;
#pragma unroll
                    for (int k2 = 0; k2 < 8; k2++)
                        sd += ps[(k2 * 2 + 0) * 256 + rcl * 64 + rb];
                    int col = hbase + rcl;
                    float ht = tanhf(whxs[tid] + sd);
                    float z  = z1s[tid];
                    float hp = __ldcg(&g_h1T[col * 64 + rb]);
                    float hn = hp + z * (ht - hp);
                    g_h1T[col * 64 + rb] = hn;
                    g_Hseq[((long)t * 64 + rb) * 512 + col] = hn;
                }
            } else {
                if (t + 1 < TT) {
                    float sb = 0.f;
#pragma unroll
                    for (int k2 = 0; k2 < 8; k2++)
                        sb += ps[(k2 * 2 + 1) * 256 + rcl * 64 + rb];
                    int col = hbase + rcl;
                    float ht = tanhf(gxw_pre + sb);
                    float z  = z0s[tid - 256];
                    float hp = __ldcg(&g_h0T[col * 64 + rb]);
                    g_h0T[col * 64 + rb] = hp + z * (ht - hp);
                }
            }
        }
        bcnt += NBLK; gridbar(bcnt);
    }
}

// ---------------- host launch ----------------------------------------------
extern "C" void kernel_launch(void* const* d_in, const int* in_sizes, int n_in,
                              void* d_out, int out_size)
{
    const int*   inputs = (const int*)  d_in[0];            // (T,B)
    const float* hidden = (const float*)d_in[1];            // (2,B,H)
    const float* embt   = (const float*)d_in[2];            // (V,E)
    const float* W_x    = (const float*)d_in[3];            // (2,H,3H)
    const float* U_h    = (const float*)d_in[4];            // (2,H,2H)
    const float* U_ht   = (const float*)d_in[5];            // (2,H,H)
    const float* b_rzh  = (const float*)d_in[6];            // (2,3H)
    const float* fc_W   = (const float*)d_in[7];            // (2,H,H)
    const float* fc_b   = (const float*)d_in[8];            // (2,H)
    const float* dec_W  = (const float*)d_in[9];            // (V,H)
    const float* dec_b  = (const float*)d_in[10];           // (V,)
    float* out = (float*)d_out;

    const float* W_x0  = W_x;
    const float* W_x1  = W_x + HH * G3;
    const float* U_h0  = U_h;
    const float* U_h1  = U_h + HH * G2;
    const float* U_ht0 = U_ht;
    const float* U_ht1 = U_ht + HH * HH;
    const float* fc0   = fc_W;
    const float* fc1   = fc_W + HH * HH;

    float* pGX0 = nullptr; cudaGetSymbolAddress((void**)&pGX0, g_gx0T);
    float* pM1  = nullptr; cudaGetSymbolAddress((void**)&pM1,  g_M1);
    float* pB1p = nullptr; cudaGetSymbolAddress((void**)&pB1p, g_b1p);
    float* pDmt = nullptr; cudaGetSymbolAddress((void**)&pDmt, g_Dmt);
    float* pDb2 = nullptr; cudaGetSymbolAddress((void**)&pDb2, g_db2);

    static bool attr_set = false;
    if (!attr_set) {
        cudaFuncSetAttribute(gru_persistent,
                             cudaFuncAttributeMaxDynamicSharedMemorySize,
                             SM_FLOATS * sizeof(float));
        cudaFuncSetAttribute(mma_decoder,
                             cudaFuncAttributeMaxDynamicSharedMemorySize,
                             DC_SMEM);
        attr_set = true;
    }

    // 0) init h (transposed) + barrier counter
    init_h<<<(BB * HH + 255) / 256, 256>>>(hidden);

    // 1) GX0^T = (gather(emb) @ W_x0 + b_rzh0) -> [t][col][b]
    gemm128<0, 0, true, true, true><<<dim3(G3 / 128, MB / 128), 256>>>(
        embt, W_x0, b_rzh, inputs, pGX0, MB, G3, HH);

    // 2) M1 = fc0^T @ W_x1, b1' = fc_b0 @ W_x1 + b_rzh1
    gemm128<1, 0, false, false, false><<<dim3(G3 / 128, HH / 128), 256>>>(
        fc0, W_x1, nullptr, nullptr, pM1, HH, G3, HH);
    compute_b1p<<<(G3 * 32 + 255) / 256, 256>>>(fc_b, W_x1, b_rzh + G3, pB1p);

    // 3) Dmt = dec_W @ fc1  (V x H), db2 = dec_W @ fc_b1 + dec_b
    gemm128<0, 0, false, false, false><<<dim3(HH / 128, (VV + 127) / 128), 256>>>(
        dec_W, fc1, nullptr, nullptr, pDmt, VV, HH, HH);
    compute_db2<<<(VV * 32 + 255) / 256, 256>>>(fc_b + HH, dec_W, dec_b, pDb2);

    // 3b) bf16 split of decoder weights (hi/lo, padded rows zeroed)
    split_D<<<(int)(((long)VPAD * HH + 255) / 256), 256>>>();

    // 4) entire 128-step recurrence in ONE persistent kernel (2 syncs/step)
    gru_persistent<<<NBLK, 512, SM_FLOATS * sizeof(float)>>>(
        U_h0, U_ht0, U_h1, U_ht1);

    // 5) bf16 split of Hseq, then mma.sync bf16 decoder GEMM
    split_H<<<(int)(((long)MB * HH + 255) / 256), 256>>>();
    mma_decoder<<<dim3(VPAD / 128, MB / 128), 256, DC_SMEM>>>(out);

    // 6) h_final appended after logits (if harness expects it)
    if (out_size >= (long)MB * VV + 2 * BB * HH) {
        write_hfinal<<<(BB * HH + 255) / 256, 256>>>(out + (long)MB * VV);
    }
}

// round 16
// speedup vs baseline: 6.7493x; 1.1039x over previous
#include <cuda_runtime.h>
#include <cuda_bf16.h>
#include <math.h>
#include <stdint.h>

// Problem constants
#define TT   128
#define BB   64
#define HH   512
#define VV   10000
#define G3   1536   // 3*H
#define G2   1024   // 2*H
#define MB   (TT*BB)   // 8192 rows
#define NBLK 128       // persistent blocks
#define CH   4         // h-columns owned per block
#define VPAD 10240     // VV padded to 128 multiple

typedef unsigned long long ull;

// ---------------- f32x2 packed-FMA helpers (Blackwell FFMA2) ---------------
__device__ __forceinline__ ull pack2(float x, float y) {
    ull r; asm("mov.b64 %0, {%1, %2};" : "=l"(r) : "f"(x), "f"(y)); return r;
}
__device__ __forceinline__ void ffma2(ull& d, ull a, ull b) {
    asm("fma.rn.f32x2 %0, %1, %2, %0;" : "+l"(d) : "l"(a), "l"(b));
}
__device__ __forceinline__ float2 unpack2(ull v) {
    float2 f; asm("mov.b64 {%0, %1}, %2;" : "=f"(f.x), "=f"(f.y) : "l"(v)); return f;
}

#define SWZ128(o) ((o) ^ (((o) >> 3) & 0x70))

__device__ __forceinline__ unsigned smem_u32(const void* p) {
    unsigned a;
    asm("{ .reg .u64 t; cvta.to.shared.u64 t, %1; cvt.u32.u64 %0, t; }"
        : "=r"(a) : "l"(p));
    return a;
}

// ---------------- device scratch (static: no allocations allowed) ----------
__device__ unsigned g_bar;                 // single grid-barrier counter
__device__ float g_h0T[HH*BB];             // transposed activations [h][b]
__device__ float g_h1T[HH*BB];
__device__ float g_rh0T[HH*BB];
__device__ float g_rh1T[HH*BB];
__device__ float g_gx0T[(long)MB*G3];      // [t][col][b]
__device__ float g_M1[HH*G3];              // fc0^T @ W_x1
__device__ float g_b1p[G3];
__device__ float g_Dmt[(long)VV*HH];       // dec_W @ fc1  (V x H)
__device__ float g_db2[VV];
__device__ float g_Hseq[(long)MB*HH];      // h1 per step, [t][b][h]
__device__ __nv_bfloat16 g_A2[(long)MB*G3];    // bf16-split A operand 8192 x 1536
__device__ __nv_bfloat16 g_B2[(long)VPAD*G3];  // bf16-split B operand 10240 x 1536

// ---------------- generic tiled GEMM 128x128x16 (FFMA2 inner) --------------
template<int OPA, int OPB, bool GATHER, bool BIAS, bool TOUT>
__global__ __launch_bounds__(256, 1)
void gemm128(const float* __restrict__ A, const float* __restrict__ B,
             const float* __restrict__ bias, const int* __restrict__ gidx,
             float* __restrict__ C, int M, int N, int K)
{
    const int BM = 128, BN = 128, BK = 16;
    __shared__ float As[BK][BM];
    __shared__ float Bs[BK][BN];
    const int m0 = blockIdx.y * BM;
    const int n0 = blockIdx.x * BN;
    const int tid = threadIdx.x;
    const int tm0 = (tid & 15) * 8;
    const int tn0 = (tid >> 4) * 8;
    ull acc[8][4];
#pragma unroll
    for (int i = 0; i < 8; i++)
#pragma unroll
        for (int j = 0; j < 4; j++) acc[i][j] = 0ULL;

    for (int k0 = 0; k0 < K; k0 += BK) {
        if (OPA == 0) {
            int kk = tid & 15, mr = tid >> 4;
#pragma unroll
            for (int i = 0; i < 8; i++) {
                int m = mr + i * 16;
                int gm = m0 + m;
                float v = 0.f;
                if (gm < M) {
                    long row = GATHER ? (long)gidx[gm] : (long)gm;
                    v = A[row * K + k0 + kk];
                }
                As[kk][m] = v;
            }
        } else {
            int m = tid & 127, kb = tid >> 7;
#pragma unroll
            for (int i = 0; i < 8; i++) {
                int kk = kb + i * 2;
                int gm = m0 + m;
                As[kk][m] = (gm < M) ? A[(long)(k0 + kk) * M + gm] : 0.f;
            }
        }
        if (OPB == 0) {
            int n = tid & 127, kb = tid >> 7;
#pragma unroll
            for (int i = 0; i < 8; i++) {
                int kk = kb + i * 2;
                int gn = n0 + n;
                Bs[kk][n] = (gn < N) ? B[(long)(k0 + kk) * N + gn] : 0.f;
            }
        } else {
            int kk = tid & 15, nr = tid >> 4;
#pragma unroll
            for (int i = 0; i < 8; i++) {
                int n = nr + i * 16;
                int gn = n0 + n;
                Bs[kk][n] = (gn < N) ? B[(long)gn * K + k0 + kk] : 0.f;
            }
        }
        __syncthreads();
#pragma unroll
        for (int kk = 0; kk < BK; kk++) {
            float a[8];
            *(float4*)&a[0] = *(const float4*)&As[kk][tm0];
            *(float4*)&a[4] = *(const float4*)&As[kk][tm0 + 4];
            ull b2[4];
            *(ulonglong2*)&b2[0] = *(const ulonglong2*)&Bs[kk][tn0];
            *(ulonglong2*)&b2[2] = *(const ulonglong2*)&Bs[kk][tn0 + 4];
#pragma unroll
            for (int i = 0; i < 8; i++) {
                ull ai = pack2(a[i], a[i]);
#pragma unroll
                for (int j = 0; j < 4; j++) ffma2(acc[i][j], ai, b2[j]);
            }
        }
        __syncthreads();
    }
#pragma unroll
    for (int i = 0; i < 8; i++) {
        int gm = m0 + tm0 + i;
        if (gm >= M) continue;
#pragma unroll
        for (int j2 = 0; j2 < 4; j2++) {
            float2 f = unpack2(acc[i][j2]);
#pragma unroll
            for (int u = 0; u < 2; u++) {
                int gn = n0 + tn0 + j2 * 2 + u;
                if (gn < N) {
                    float v = (u == 0) ? f.x : f.y;
                    if (BIAS) v += bias[gn];
                    long idx = TOUT ? (((long)(gm >> 6) * N + gn) * 64 + (gm & 63))
                                    : ((long)gm * N + gn);
                    C[idx] = v;
                }
            }
        }
    }
}

// ---------------- one-time small precomputes -------------------------------
__global__ void compute_b1p(const float* __restrict__ fcb0,
                            const float* __restrict__ Wx1,
                            const float* __restrict__ brzh1,
                            float* __restrict__ out)
{
    int wj = (blockIdx.x * 256 + threadIdx.x) >> 5;
    int lane = threadIdx.x & 31;
    if (wj >= G3) return;
    float s = 0.f;
    for (int m = lane; m < HH; m += 32)
        s += __ldg(&fcb0[m]) * __ldg(&Wx1[m * G3 + wj]);
#pragma unroll
    for (int o = 16; o; o >>= 1) s += __shfl_xor_sync(0xffffffffu, s, o);
    if (lane == 0) out[wj] = s + brzh1[wj];
}

__global__ void compute_db2(const float* __restrict__ fcb1,
                            const float* __restrict__ decW,
                            const float* __restrict__ decb,
                            float* __restrict__ out)
{
    int v = (blockIdx.x * 256 + threadIdx.x) >> 5;
    int lane = threadIdx.x & 31;
    if (v >= VV) return;
    float s = 0.f;
    for (int j = lane; j < HH; j += 32) s += fcb1[j] * decW[v * HH + j];
#pragma unroll
    for (int o = 16; o; o >>= 1) s += __shfl_xor_sync(0xffffffffu, s, o);
    if (lane == 0) out[v] = s + decb[v];
}

// bf16 hi/lo split of decoder weights: B2 = [Dh | Dl | Dh] (rows padded)
__global__ void split_D()
{
    long i = (long)blockIdx.x * 256 + threadIdx.x;
    if (i >= (long)VPAD * HH) return;
    long v = i >> 9; int k = (int)(i & 511);
    __nv_bfloat16 hi, lo;
    if (v < VV) {
        float x = g_Dmt[v * HH + k];
        hi = __float2bfloat16(x);
        lo = __float2bfloat16(x - __bfloat162float(hi));
    } else {
        hi = __float2bfloat16(0.f); lo = hi;
    }
    long base = v * G3 + k;
    g_B2[base]        = hi;
    g_B2[base + 512]  = lo;
    g_B2[base + 1024] = hi;
}

// bf16 hi/lo split of Hseq: A2 = [Hh | Hh | Hl]
__global__ void split_H()
{
    long i = (long)blockIdx.x * 256 + threadIdx.x;
    if (i >= (long)MB * HH) return;
    long m = i >> 9; int k = (int)(i & 511);
    float x = g_Hseq[m * HH + k];
    __nv_bfloat16 hi = __float2bfloat16(x);
    __nv_bfloat16 lo = __float2bfloat16(x - __bfloat162float(hi));
    long base = m * G3 + k;
    g_A2[base]        = hi;
    g_A2[base + 512]  = hi;
    g_A2[base + 1024] = lo;
}

// gathered-embedding bf16 split: A2 rows m=t*64+b = emb_table[inputs[m]]
__global__ void split_E(const int* __restrict__ inputs,
                        const float* __restrict__ emb)
{
    long i = (long)blockIdx.x * 256 + threadIdx.x;
    if (i >= (long)MB * HH) return;
    long m = i >> 9; int k = (int)(i & 511);
    int tok = __ldg(&inputs[m]);
    float x = __ldg(&emb[(long)tok * HH + k]);
    __nv_bfloat16 hi = __float2bfloat16(x);
    __nv_bfloat16 lo = __float2bfloat16(x - __bfloat162float(hi));
    long base = m * G3 + k;
    g_A2[base]        = hi;
    g_A2[base + 512]  = hi;
    g_A2[base + 1024] = lo;
}

// W_x0 transpose-split: B2 row n (0..1535) = column n of W_x0, [Wh|Wl|Wh]
__global__ void split_W0(const float* __restrict__ Wx0)
{
    long i = (long)blockIdx.x * 256 + threadIdx.x;
    if (i >= (long)G3 * HH) return;
    long n = i >> 9; int k = (int)(i & 511);
    float x = __ldg(&Wx0[(long)k * G3 + n]);
    __nv_bfloat16 hi = __float2bfloat16(x);
    __nv_bfloat16 lo = __float2bfloat16(x - __bfloat162float(hi));
    long base = n * G3 + k;
    g_B2[base]        = hi;
    g_B2[base + 512]  = lo;
    g_B2[base + 1024] = hi;
}

__global__ void init_h(const float* __restrict__ hidden)
{
    int i = blockIdx.x * 256 + threadIdx.x;
    if (i == 0) g_bar = 0u;
    if (i < BB * HH) {
        int b = i >> 9, h = i & 511;
        g_h0T[h * 64 + b] = hidden[i];
        g_h1T[h * 64 + b] = hidden[BB * HH + i];
    }
}

__global__ void write_hfinal(float* __restrict__ out)
{
    int i = blockIdx.x * 256 + threadIdx.x;
    if (i < BB * HH) {
        int b = i >> 9, h = i & 511;
        out[i] = g_h0T[h * 64 + b];
        out[BB * HH + i] = g_h1T[h * 64 + b];
    }
}

// ---------------- shared mma tile-core macros ------------------------------
#define DC_NCH  24          // 1536 / 64
#define DC_SMEM 66560       // 1024 align slack + 2*16K(A) + 2*16K(B)

// ---------------- mma.sync bf16 decoder GEMM -------------------------------
// out[8192 x 10000] = A2 @ B2^T + db2 ; tile 128x128, 8 warps (64x32/warp).
__global__ __launch_bounds__(256, 2)
void mma_decoder(float* __restrict__ out)
{
    extern __shared__ char dsm_raw[];
    char* dsm = (char*)(((uintptr_t)dsm_raw + 1023) & ~(uintptr_t)1023);
    char* bufA[2] = { dsm,          dsm + 16384 };
    char* bufB[2] = { dsm + 32768,  dsm + 49152 };

    const int tid  = threadIdx.x;
    const int wid  = tid >> 5;
    const int lane = tid & 31;
    const long m0  = (long)blockIdx.y * 128;
    const long n0t = (long)blockIdx.x * 128;
    const int wm = wid & 1;
    const int wn = wid >> 1;

    float acc[4][4][4];
#pragma unroll
    for (int i = 0; i < 4; i++)
#pragma unroll
        for (int j = 0; j < 4; j++)
#pragma unroll
            for (int q = 0; q < 4; q++) acc[i][j][q] = 0.f;

    const int lrow = tid >> 3, lseg = tid & 7;

#define LOAD_CHUNK(c) do {                                                    \
    int _kc = (c) * 64; int _bf = (c) & 1;                                    \
    _Pragma("unroll")                                                         \
    for (int _i = 0; _i < 4; _i++) {                                          \
        int _row = lrow + _i * 32;                                            \
        uint4 _v = __ldg((const uint4*)(g_A2 + (m0 + _row) * G3 + _kc) + lseg); \
        *(uint4*)(bufA[_bf] + SWZ128(_row * 128 + lseg * 16)) = _v;           \
        uint4 _w = __ldg((const uint4*)(g_B2 + (n0t + _row) * G3 + _kc) + lseg); \
        *(uint4*)(bufB[_bf] + SWZ128(_row * 128 + lseg * 16)) = _w;           \
    }                                                                         \
} while (0)

    LOAD_CHUNK(0);
    __syncthreads();

    for (int c = 0; c < DC_NCH; c++) {
        if (c + 1 < DC_NCH) LOAD_CHUNK(c + 1);
        const unsigned abase = smem_u32(bufA[c & 1]);
        const unsigned bbase = smem_u32(bufB[c & 1]);
#pragma unroll
        for (int kk = 0; kk < 64; kk += 16) {
            unsigned a[4][4];
#pragma unroll
            for (int mi = 0; mi < 4; mi++) {
                int row  = wm * 64 + mi * 16 + (lane & 15);
                int colB = kk * 2 + (lane >> 4) * 16;
                unsigned ad = abase + SWZ128(row * 128 + colB);
                asm volatile("ldmatrix.sync.aligned.m8n8.x4.shared.b16 "
                             "{%0,%1,%2,%3}, [%4];"
                             : "=r"(a[mi][0]), "=r"(a[mi][1]),
                               "=r"(a[mi][2]), "=r"(a[mi][3]) : "r"(ad));
            }
            unsigned b[4][2];
#pragma unroll
            for (int nb = 0; nb < 2; nb++) {
                int row  = wn * 32 + nb * 16 + ((lane >> 4) & 1) * 8 + (lane & 7);
                int colB = kk * 2 + ((lane >> 3) & 1) * 16;
                unsigned bd = bbase + SWZ128(row * 128 + colB);
                unsigned r0, r1, r2, r3;
                asm volatile("ldmatrix.sync.aligned.m8n8.x4.shared.b16 "
                             "{%0,%1,%2,%3}, [%4];"
                             : "=r"(r0), "=r"(r1), "=r"(r2), "=r"(r3) : "r"(bd));
                b[nb * 2][0] = r0;     b[nb * 2][1] = r1;
                b[nb * 2 + 1][0] = r2; b[nb * 2 + 1][1] = r3;
            }
#pragma unroll
            for (int mi = 0; mi < 4; mi++)
#pragma unroll
                for (int ni = 0; ni < 4; ni++)
                    asm volatile(
                        "mma.sync.aligned.m16n8k16.row.col.f32.bf16.bf16.f32 "
                        "{%0,%1,%2,%3}, {%4,%5,%6,%7}, {%8,%9}, {%0,%1,%2,%3};"
                        : "+f"(acc[mi][ni][0]), "+f"(acc[mi][ni][1]),
                          "+f"(acc[mi][ni][2]), "+f"(acc[mi][ni][3])
                        : "r"(a[mi][0]), "r"(a[mi][1]),
                          "r"(a[mi][2]), "r"(a[mi][3]),
                          "r"(b[ni][0]), "r"(b[ni][1]));
        }
        __syncthreads();
    }
#undef LOAD_CHUNK

#pragma unroll
    for (int mi = 0; mi < 4; mi++) {
        long r0 = m0 + wm * 64 + mi * 16 + (lane >> 2);
        float* op0 = out + r0 * VV;
        float* op1 = out + (r0 + 8) * VV;
#pragma unroll
        for (int ni = 0; ni < 4; ni++) {
            long n = n0t + wn * 32 + ni * 8 + (lane & 3) * 2;
            if (n + 1 < VV) {
                float d0 = __ldg(&g_db2[n]), d1 = __ldg(&g_db2[n + 1]);
                op0[n]     = acc[mi][ni][0] + d0;
                op0[n + 1] = acc[mi][ni][1] + d1;
                op1[n]     = acc[mi][ni][2] + d0;
                op1[n + 1] = acc[mi][ni][3] + d1;
            } else {
                if (n < VV) {
                    float d0 = __ldg(&g_db2[n]);
                    op0[n] = acc[mi][ni][0] + d0;
                    op1[n] = acc[mi][ni][2] + d0;
                }
            }
        }
    }
}

// ---------------- mma.sync bf16 GX0 GEMM -----------------------------------
// g_gx0T[(t*G3+n)*64+b] = (E_gathered @ W_x0)[m=t*64+b][n] + b_rzh0[n]
// A2 = split emb rows (8192 x 1536), B2 rows 0..1535 = split W_x0 columns.
__global__ __launch_bounds__(256, 2)
void mma_gx0(const float* __restrict__ bias)
{
    extern __shared__ char dsm_raw[];
    char* dsm = (char*)(((uintptr_t)dsm_raw + 1023) & ~(uintptr_t)1023);
    char* bufA[2] = { dsm,          dsm + 16384 };
    char* bufB[2] = { dsm + 32768,  dsm + 49152 };

    const int tid  = threadIdx.x;
    const int wid  = tid >> 5;
    const int lane = tid & 31;
    const long m0  = (long)blockIdx.y * 128;
    const long n0t = (long)blockIdx.x * 128;
    const int wm = wid & 1;
    const int wn = wid >> 1;

    float acc[4][4][4];
#pragma unroll
    for (int i = 0; i < 4; i++)
#pragma unroll
        for (int j = 0; j < 4; j++)
#pragma unroll
            for (int q = 0; q < 4; q++) acc[i][j][q] = 0.f;

    const int lrow = tid >> 3, lseg = tid & 7;

#define LOAD_CHUNK(c) do {                                                    \
    int _kc = (c) * 64; int _bf = (c) & 1;                                    \
    _Pragma("unroll")                                                         \
    for (int _i = 0; _i < 4; _i++) {                                          \
        int _row = lrow + _i * 32;                                            \
        uint4 _v = __ldg((const uint4*)(g_A2 + (m0 + _row) * G3 + _kc) + lseg); \
        *(uint4*)(bufA[_bf] + SWZ128(_row * 128 + lseg * 16)) = _v;           \
        uint4 _w = __ldg((const uint4*)(g_B2 + (n0t + _row) * G3 + _kc) + lseg); \
        *(uint4*)(bufB[_bf] + SWZ128(_row * 128 + lseg * 16)) = _w;           \
    }                                                                         \
} while (0)

    LOAD_CHUNK(0);
    __syncthreads();

    for (int c = 0; c < DC_NCH; c++) {
        if (c + 1 < DC_NCH) LOAD_CHUNK(c + 1);
        const unsigned abase = smem_u32(bufA[c & 1]);
        const unsigned bbase = smem_u32(bufB[c & 1]);
#pragma unroll
        for (int kk = 0; kk < 64; kk += 16) {
            unsigned a[4][4];
#pragma unroll
            for (int mi = 0; mi < 4; mi++) {
                int row  = wm * 64 + mi * 16 + (lane & 15);
                int colB = kk * 2 + (lane >> 4) * 16;
                unsigned ad = abase + SWZ128(row * 128 + colB);
                asm volatile("ldmatrix.sync.aligned.m8n8.x4.shared.b16 "
                             "{%0,%1,%2,%3}, [%4];"
                             : "=r"(a[mi][0]), "=r"(a[mi][1]),
                               "=r"(a[mi][2]), "=r"(a[mi][3]) : "r"(ad));
            }
            unsigned b[4][2];
#pragma unroll
            for (int nb = 0; nb < 2; nb++) {
                int row  = wn * 32 + nb * 16 + ((lane >> 4) & 1) * 8 + (lane & 7);
                int colB = kk * 2 + ((lane >> 3) & 1) * 16;
                unsigned bd = bbase + SWZ128(row * 128 + colB);
                unsigned r0, r1, r2, r3;
                asm volatile("ldmatrix.sync.aligned.m8n8.x4.shared.b16 "
                             "{%0,%1,%2,%3}, [%4];"
                             : "=r"(r0), "=r"(r1), "=r"(r2), "=r"(r3) : "r"(bd));
                b[nb * 2][0] = r0;     b[nb * 2][1] = r1;
                b[nb * 2 + 1][0] = r2; b[nb * 2 + 1][1] = r3;
            }
#pragma unroll
            for (int mi = 0; mi < 4; mi++)
#pragma unroll
                for (int ni = 0; ni < 4; ni++)
                    asm volatile(
                        "mma.sync.aligned.m16n8k16.row.col.f32.bf16.bf16.f32 "
                        "{%0,%1,%2,%3}, {%4,%5,%6,%7}, {%8,%9}, {%0,%1,%2,%3};"
                        : "+f"(acc[mi][ni][0]), "+f"(acc[mi][ni][1]),
                          "+f"(acc[mi][ni][2]), "+f"(acc[mi][ni][3])
                        : "r"(a[mi][0]), "r"(a[mi][1]),
                          "r"(a[mi][2]), "r"(a[mi][3]),
                          "r"(b[ni][0]), "r"(b[ni][1]));
        }
        __syncthreads();
    }
#undef LOAD_CHUNK

    // epilogue: TOUT layout ((m>>6)*G3 + n)*64 + (m&63), + bias[n]
#pragma unroll
    for (int mi = 0; mi < 4; mi++) {
        long r0 = m0 + wm * 64 + mi * 16 + (lane >> 2);
        long r1 = r0 + 8;
        long t0 = r0 >> 6; int b0i = (int)(r0 & 63);
        long t1 = r1 >> 6; int b1i = (int)(r1 & 63);
#pragma unroll
        for (int ni = 0; ni < 4; ni++) {
            long n = n0t + wn * 32 + ni * 8 + (lane & 3) * 2;
            float d0 = __ldg(&bias[n]), d1 = __ldg(&bias[n + 1]);
            g_gx0T[(t0 * G3 + n)     * 64 + b0i] = acc[mi][ni][0] + d0;
            g_gx0T[(t0 * G3 + n + 1) * 64 + b0i] = acc[mi][ni][1] + d1;
            g_gx0T[(t1 * G3 + n)     * 64 + b1i] = acc[mi][ni][2] + d0;
            g_gx0T[(t1 * G3 + n + 1) * 64 + b1i] = acc[mi][ni][3] + d1;
        }
    }
}

// ---------------- fence-free grid barrier ----------------------------------
// arrival: red.release.gpu (release publishes all block writes via the
// preceding __syncthreads happens-before chain — the CG grid.sync pattern);
// wait: ld.acquire.gpu poll (acquire synchronizes with every releaser).
// No explicit fence.gpu -> no CCTL.IVALL L1 flush per barrier.
__device__ __forceinline__ void gridbar(unsigned target)
{
    __syncthreads();
    if (threadIdx.x == 0) {
        asm volatile("red.release.gpu.global.add.u32 [%0], 1;" :: "l"(&g_bar) : "memory");
        unsigned v;
        do {
            asm volatile("ld.acquire.gpu.global.u32 %0, [%1];"
                         : "=r"(v) : "l"(&g_bar) : "memory");
        } while (v < target);
    }
    __syncthreads();
}

// smem layout (floats):
//   w[9*512*4]=18432 | bufs[2*8192]=16384 | ps[7*8*256]=14336 |
//   z0s[256] | z1s[256] | whxs[256]
#define SM_W   0
#define SM_BUF 18432
#define SM_PS  34816
#define SM_Z0  49152
#define SM_Z1  49408
#define SM_WX  49664
#define SM_FLOATS 49920   // 199680 bytes

// ---------------- persistent recurrent kernel (2 barriers / step) ----------
__global__ __launch_bounds__(512, 1)
void gru_persistent(const float* __restrict__ Uh0, const float* __restrict__ Uht0,
                    const float* __restrict__ Uh1, const float* __restrict__ Uht1)
{
    extern __shared__ float sm[];
    float* w    = sm + SM_W;   // groups: 0=Uh0r 1=Uh0z 2=Uht0 3=M1r 4=M1z 5=M1w 6=Uh1r 7=Uh1z 8=Uht1
    float* bufs = sm + SM_BUF;
    float* ps   = sm + SM_PS;
    float* z0s  = sm + SM_Z0;
    float* z1s  = sm + SM_Z1;
    float* whxs = sm + SM_WX;

    const int tid   = threadIdx.x;
    const int hbase = blockIdx.x * CH;

    for (int i = tid; i < 9 * 512 * 4; i += 512) {
        int c = i & 3, k = (i >> 2) & 511, g = i >> 11;
        float v;
        switch (g) {
            case 0:  v = Uh0[k * G2 + hbase + c]; break;
            case 1:  v = Uh0[k * G2 + 512 + hbase + c]; break;
            case 2:  v = Uht0[k * HH + hbase + c]; break;
            case 3:  v = g_M1[k * G3 + hbase + c]; break;
            case 4:  v = g_M1[k * G3 + 512 + hbase + c]; break;
            case 5:  v = g_M1[k * G3 + 1024 + hbase + c]; break;
            case 6:  v = Uh1[k * G2 + hbase + c]; break;
            case 7:  v = Uh1[k * G2 + 512 + hbase + c]; break;
            default: v = Uht1[k * HH + hbase + c]; break;
        }
        w[i] = v;
    }
    __syncthreads();

    const int b   = tid & 63;
    const int ks  = tid >> 6;
    const int rb  = tid & 63;
    const int rcl = (tid >> 6) & 3;
    unsigned bcnt = 0;

    for (int t = -1; t < TT; t++) {
        const int tp1 = (t + 1 < TT) ? t + 1 : TT - 1;
        const bool doC = (t >= 0);

        // ========= Stage X: C(t) || A(t+1) =========
        {
            float gxr_pre = 0.f, gxz_pre = 0.f;
            if (tid >= 256) {
                gxr_pre = __ldg(&g_gx0T[((long)tp1 * G3 +       hbase + rcl) * 64 + rb]);
                gxz_pre = __ldg(&g_gx0T[((long)tp1 * G3 + 512 + hbase + rcl) * 64 + rb]);
            }
            ull a3x=0,a3y=0,a4x=0,a4y=0,a5x=0,a5y=0;
            ull a0x=0,a0y=0,a1x=0,a1y=0;
            ull a6x=0,a6y=0,a7x=0,a7y=0;
            const float4* s0 = (const float4*)g_h0T;
            const float4* s1 = (const float4*)g_h1T;
            float4 p0 = __ldcg(s0 + tid),        p1 = __ldcg(s0 + 512 + tid),
                   p2 = __ldcg(s0 + 1024 + tid), p3 = __ldcg(s0 + 1536 + tid);
#pragma unroll
            for (int ph = 0; ph < 8; ph++) {
                float* bp = bufs + (ph & 1) * 8192;
                ((float4*)bp)[tid] = p0; ((float4*)bp)[512 + tid] = p1;
                ((float4*)bp)[1024 + tid] = p2; ((float4*)bp)[1536 + tid] = p3;
                __syncthreads();
                if (ph < 7) {
                    const float4* sn = (ph + 1 < 4) ? s0 : s1;
                    const float4* sc = sn + ((ph + 1) & 3) * 2048;
                    p0 = __ldcg(sc + tid); p1 = __ldcg(sc + 512 + tid);
                    p2 = __ldcg(sc + 1024 + tid); p3 = __ldcg(sc + 1536 + tid);
                }
                const float* ap = bp + (ks * 16) * 64 + b;
                const int kk = ((ph & 3) * 128 + ks * 16) * 4;
                if (ph < 4) {
                    const float* w3 = w + 3 * 2048 + kk;
                    const float* w4 = w + 4 * 2048 + kk;
                    const float* w5 = w + 5 * 2048 + kk;
                    const float* w0 = w + 0 * 2048 + kk;
                    const float* w1 = w + 1 * 2048 + kk;
#pragma unroll
                    for (int j = 0; j < 16; j++) {
                        float a = ap[j * 64]; ull a2 = pack2(a, a);
                        ulonglong2 v3 = *(const ulonglong2*)(w3 + j * 4);
                        ulonglong2 v4 = *(const ulonglong2*)(w4 + j * 4);
                        ulonglong2 v5 = *(const ulonglong2*)(w5 + j * 4);
                        ulonglong2 v0 = *(const ulonglong2*)(w0 + j * 4);
                        ulonglong2 v1 = *(const ulonglong2*)(w1 + j * 4);
                        ffma2(a3x, a2, v3.x); ffma2(a3y, a2, v3.y);
                        ffma2(a4x, a2, v4.x); ffma2(a4y, a2, v4.y);
                        ffma2(a5x, a2, v5.x); ffma2(a5y, a2, v5.y);
                        ffma2(a0x, a2, v0.x); ffma2(a0y, a2, v0.y);
                        ffma2(a1x, a2, v1.x); ffma2(a1y, a2, v1.y);
                    }
                } else {
                    const float* w6 = w + 6 * 2048 + kk;
                    const float* w7 = w + 7 * 2048 + kk;
#pragma unroll
                    for (int j = 0; j < 16; j++) {
                        float a = ap[j * 64]; ull a2 = pack2(a, a);
                        ulonglong2 v6 = *(const ulonglong2*)(w6 + j * 4);
                        ulonglong2 v7 = *(const ulonglong2*)(w7 + j * 4);
                        ffma2(a6x, a2, v6.x); ffma2(a6y, a2, v6.y);
                        ffma2(a7x, a2, v7.x); ffma2(a7y, a2, v7.y);
                    }
                }
            }
            {
                float2 f; float* pp;
                pp = ps + (ks * 7 + 0) * 256 + b;
                f = unpack2(a3x); pp[0] = f.x; pp[64] = f.y;
                f = unpack2(a3y); pp[128] = f.x; pp[192] = f.y;
                pp = ps + (ks * 7 + 1) * 256 + b;
                f = unpack2(a4x); pp[0] = f.x; pp[64] = f.y;
                f = unpack2(a4y); pp[128] = f.x; pp[192] = f.y;
                pp = ps + (ks * 7 + 2) * 256 + b;
                f = unpack2(a5x); pp[0] = f.x; pp[64] = f.y;
                f = unpack2(a5y); pp[128] = f.x; pp[192] = f.y;
                pp = ps + (ks * 7 + 3) * 256 + b;
                f = unpack2(a6x); pp[0] = f.x; pp[64] = f.y;
                f = unpack2(a6y); pp[128] = f.x; pp[192] = f.y;
                pp = ps + (ks * 7 + 4) * 256 + b;
                f = unpack2(a7x); pp[0] = f.x; pp[64] = f.y;
                f = unpack2(a7y); pp[128] = f.x; pp[192] = f.y;
                pp = ps + (ks * 7 + 5) * 256 + b;
                f = unpack2(a0x); pp[0] = f.x; pp[64] = f.y;
                f = unpack2(a0y); pp[128] = f.x; pp[192] = f.y;
                pp = ps + (ks * 7 + 6) * 256 + b;
                f = unpack2(a1x); pp[0] = f.x; pp[64] = f.y;
                f = unpack2(a1y); pp[128] = f.x; pp[192] = f.y;
            }
            __syncthreads();
            if (tid < 256) {
                if (doC) {
                    float sr = 0.f, sz = 0.f, sw = 0.f;
#pragma unroll
                    for (int k2 = 0; k2 < 8; k2++) {
                        int base = k2 * 7 * 256 + rcl * 64 + rb;
                        sr += ps[base]           + ps[base + 3 * 256];
                        sz += ps[base + 256]     + ps[base + 4 * 256];
                        sw += ps[base + 2 * 256];
                    }
                    int col = hbase + rcl;
                    float r1v = 1.f / (1.f + expf(-(sr + __ldg(&g_b1p[col]))));
                    float z1v = 1.f / (1.f + expf(-(sz + __ldg(&g_b1p[512 + col]))));
                    float wx  = sw + __ldg(&g_b1p[1024 + col]);
                    float h1v = __ldcg(&g_h1T[col * 64 + rb]);
                    g_rh1T[col * 64 + rb] = r1v * h1v;
                    z1s[tid]  = z1v;
                    whxs[tid] = wx;
                }
            } else {
                float ar = 0.f, az = 0.f;
#pragma unroll
                for (int k2 = 0; k2 < 8; k2++) {
                    int base = k2 * 7 * 256 + rcl * 64 + rb;
                    ar += ps[base + 5 * 256];
                    az += ps[base + 6 * 256];
                }
                int col = hbase + rcl;
                float r0v = 1.f / (1.f + expf(-(ar + gxr_pre)));
                float z0v = 1.f / (1.f + expf(-(az + gxz_pre)));
                g_rh0T[col * 64 + rb] = r0v * __ldcg(&g_h0T[col * 64 + rb]);
                z0s[tid - 256] = z0v;
            }
        }
        bcnt += NBLK; gridbar(bcnt);

        // ========= Stage Y: D(t) || B(t+1) =========
        {
            float gxw_pre = 0.f;
            if (tid >= 256)
                gxw_pre = __ldg(&g_gx0T[((long)tp1 * G3 + 1024 + hbase + rcl) * 64 + rb]);
            ull d0 = 0, d1 = 0, e0 = 0, e1 = 0;
            const float4* sD = (const float4*)g_rh1T;
            const float4* sB = (const float4*)g_rh0T;
            float4 p0 = __ldcg(sD + tid),        p1 = __ldcg(sD + 512 + tid),
                   p2 = __ldcg(sD + 1024 + tid), p3 = __ldcg(sD + 1536 + tid);
#pragma unroll
            for (int ph = 0; ph < 8; ph++) {
                float* bp = bufs + (ph & 1) * 8192;
                ((float4*)bp)[tid] = p0; ((float4*)bp)[512 + tid] = p1;
                ((float4*)bp)[1024 + tid] = p2; ((float4*)bp)[1536 + tid] = p3;
                __syncthreads();
                if (ph < 7) {
                    const float4* sn = (ph + 1 < 4) ? sD : sB;
                    const float4* sc = sn + ((ph + 1) & 3) * 2048;
                    p0 = __ldcg(sc + tid); p1 = __ldcg(sc + 512 + tid);
                    p2 = __ldcg(sc + 1024 + tid); p3 = __ldcg(sc + 1536 + tid);
                }
                const float* ap = bp + (ks * 16) * 64 + b;
                const int kk = ((ph & 3) * 128 + ks * 16) * 4;
                if (ph < 4) {
                    const float* w8 = w + 8 * 2048 + kk;
#pragma unroll
                    for (int j = 0; j < 16; j++) {
                        float a = ap[j * 64]; ull a2 = pack2(a, a);
                        ulonglong2 v8 = *(const ulonglong2*)(w8 + j * 4);
                        ffma2(d0, a2, v8.x); ffma2(d1, a2, v8.y);
                    }
                } else {
                    const float* w2 = w + 2 * 2048 + kk;
#pragma unroll
                    for (int j = 0; j < 16; j++) {
                        float a = ap[j * 64]; ull a2 = pack2(a, a);
                        ulonglong2 v2 = *(const ulonglong2*)(w2 + j * 4);
                        ffma2(e0, a2, v2.x); ffma2(e1, a2, v2.y);
                    }
                }
            }
            {
                float2 f; float* pp;
                pp = ps + (ks * 2 + 0) * 256 + b;
                f = unpack2(d0); pp[0] = f.x; pp[64] = f.y;
                f = unpack2(d1); pp[128] = f.x; pp[192] = f.y;
                pp = ps + (ks * 2 + 1) * 256 + b;
                f = unpack2(e0); pp[0] = f.x; pp[64] = f.y;
                f = unpack2(e1); pp[128] = f.x; pp[192] = f.y;
            }
            __syncthreads();
            if (tid < 256) {
                if (doC) {
                    float sd = 0.f;
#pragma unroll
                    for (int k2 = 0; k2 < 8; k2++)
                        sd += ps[(k2 * 2 + 0) * 256 + rcl * 64 + rb];
                    int col = hbase + rcl;
                    float ht = tanhf(whxs[tid] + sd);
                    float z  = z1s[tid];
                    float hp = __ldcg(&g_h1T[col * 64 + rb]);
                    float hn = hp + z * (ht - hp);
                    g_h1T[col * 64 + rb] = hn;
                    g_Hseq[((long)t * 64 + rb) * 512 + col] = hn;
                }
            } else {
                if (t + 1 < TT) {
                    float sb = 0.f;
#pragma unroll
                    for (int k2 = 0; k2 < 8; k2++)
                        sb += ps[(k2 * 2 + 1) * 256 + rcl * 64 + rb];
                    int col = hbase + rcl;
                    float ht = tanhf(gxw_pre + sb);
                    float z  = z0s[tid - 256];
                    float hp = __ldcg(&g_h0T[col * 64 + rb]);
                    g_h0T[col * 64 + rb] = hp + z * (ht - hp);
                }
            }
        }
        bcnt += NBLK; gridbar(bcnt);
    }
}

// ---------------- host launch ----------------------------------------------
extern "C" void kernel_launch(void* const* d_in, const int* in_sizes, int n_in,
                              void* d_out, int out_size)
{
    const int*   inputs = (const int*)  d_in[0];            // (T,B)
    const float* hidden = (const float*)d_in[1];            // (2,B,H)
    const float* embt   = (const float*)d_in[2];            // (V,E)
    const float* W_x    = (const float*)d_in[3];            // (2,H,3H)
    const float* U_h    = (const float*)d_in[4];            // (2,H,2H)
    const float* U_ht   = (const float*)d_in[5];            // (2,H,H)
    const float* b_rzh  = (const float*)d_in[6];            // (2,3H)
    const float* fc_W   = (const float*)d_in[7];            // (2,H,H)
    const float* fc_b   = (const float*)d_in[8];            // (2,H)
    const float* dec_W  = (const float*)d_in[9];            // (V,H)
    const float* dec_b  = (const float*)d_in[10];           // (V,)
    float* out = (float*)d_out;

    const float* W_x0  = W_x;
    const float* W_x1  = W_x + HH * G3;
    const float* U_h0  = U_h;
    const float* U_h1  = U_h + HH * G2;
    const float* U_ht0 = U_ht;
    const float* U_ht1 = U_ht + HH * HH;
    const float* fc0   = fc_W;
    const float* fc1   = fc_W + HH * HH;

    float* pM1  = nullptr; cudaGetSymbolAddress((void**)&pM1,  g_M1);
    float* pB1p = nullptr; cudaGetSymbolAddress((void**)&pB1p, g_b1p);
    float* pDmt = nullptr; cudaGetSymbolAddress((void**)&pDmt, g_Dmt);
    float* pDb2 = nullptr; cudaGetSymbolAddress((void**)&pDb2, g_db2);

    static bool attr_set = false;
    if (!attr_set) {
        cudaFuncSetAttribute(gru_persistent,
                             cudaFuncAttributeMaxDynamicSharedMemorySize,
                             SM_FLOATS * sizeof(float));
        cudaFuncSetAttribute(mma_decoder,
                             cudaFuncAttributeMaxDynamicSharedMemorySize,
                             DC_SMEM);
        cudaFuncSetAttribute(mma_gx0,
                             cudaFuncAttributeMaxDynamicSharedMemorySize,
                             DC_SMEM);
        attr_set = true;
    }

    // 0) init h (transposed) + barrier counter
    init_h<<<(BB * HH + 255) / 256, 256>>>(hidden);

    // 1) GX0 via tensor cores: split gathered emb + W_x0, then mma
    split_E<<<(int)(((long)MB * HH + 255) / 256), 256>>>(inputs, embt);
    split_W0<<<(int)(((long)G3 * HH + 255) / 256), 256>>>(W_x0);
    mma_gx0<<<dim3(G3 / 128, MB / 128), 256, DC_SMEM>>>(b_rzh);

    // 2) M1 = fc0^T @ W_x1, b1' = fc_b0 @ W_x1 + b_rzh1
    gemm128<1, 0, false, false, false><<<dim3(G3 / 128, HH / 128), 256>>>(
        fc0, W_x1, nullptr, nullptr, pM1, HH, G3, HH);
    compute_b1p<<<(G3 * 32 + 255) / 256, 256>>>(fc_b, W_x1, b_rzh + G3, pB1p);

    // 3) Dmt = dec_W @ fc1  (V x H), db2 = dec_W @ fc_b1 + dec_b
    gemm128<0, 0, false, false, false><<<dim3(HH / 128, (VV + 127) / 128), 256>>>(
        dec_W, fc1, nullptr, nullptr, pDmt, VV, HH, HH);
    compute_db2<<<(VV * 32 + 255) / 256, 256>>>(fc_b + HH, dec_W, dec_b, pDb2);

    // 3b) bf16 split of decoder weights (overwrites g_B2 AFTER mma_gx0 ran)
    split_D<<<(int)(((long)VPAD * HH + 255) / 256), 256>>>();

    // 4) entire 128-step recurrence in ONE persistent kernel (2 syncs/step)
    gru_persistent<<<NBLK, 512, SM_FLOATS * sizeof(float)>>>(
        U_h0, U_ht0, U_h1, U_ht1);

    // 5) bf16 split of Hseq, then mma.sync bf16 decoder GEMM
    split_H<<<(int)(((long)MB * HH + 255) / 256), 256>>>();
    mma_decoder<<<dim3(VPAD / 128, MB / 128), 256, DC_SMEM>>>(out);

    // 6) h_final appended after logits (if harness expects it)
    if (out_size >= (long)MB * VV + 2 * BB * HH) {
        write_hfinal<<<(BB * HH + 255) / 256, 256>>>(out + (long)MB * VV);
    }
}